// round 3
// baseline (speedup 1.0000x reference)
#include <cuda_runtime.h>
#include <math.h>

#define NQ 4
#define DH 128
#define DIN 64
#define DOUT 32
#define PI_HALF 1.5707963267948966f
#define RSQRT2 0.7071067811865476f

#define MAXN 20000
#define MAXE 300000
#define MAXE2 (MAXN + MAXE)

// ---------------- scratch (static device allocations; no cudaMalloc) ----------------
__device__ float g_h[MAXN * DH];
__device__ float g_hn[MAXN * DH];
__device__ float g_xc[MAXN * DH];
__device__ float g_q[MAXN * NQ];
__device__ float g_k[MAXN * NQ];
__device__ float g_xq[MAXN * NQ];
__device__ float g_att[MAXE2];
__device__ float g_partial[4096];
__device__ float g_expsum;
__device__ int   g_cnt[MAXN + 1];
__device__ int   g_off[MAXN + 1];
__device__ int   g_cur[MAXN];
__device__ int2  g_csr[MAXE2];     // .x = edge id, .y = src node
__device__ float g_rot[36 * 8];    // [0..15] ent, [16..23] att, [24..35] path
__device__ float g_M[DOUT * NQ];   // fused path_out -> out
__device__ float g_C[DOUT];

// ---------------- setup: rot matrices + fused output linear ----------------
// Rot(phi,theta,omega) = RZ(om) RY(th) RZ(phi):
// U00 = e^{-i(phi+om)/2} c ; U01 = -e^{+i(phi-om)/2} s
// U10 = e^{-i(phi-om)/2} s ; U11 = e^{+i(phi+om)/2} c
__global__ void setup_kernel(const float* __restrict__ ent, const float* __restrict__ attqp,
                             const float* __restrict__ path,
                             const float* __restrict__ poW, const float* __restrict__ pob,
                             const float* __restrict__ oW, const float* __restrict__ ob)
{
    int t = threadIdx.x;
    if (t < 36) {
        const float* p;
        if (t < 16)      p = ent + t * 3;           // [2,2,4,3] flattens to exactly t
        else if (t < 24) p = attqp + (t - 16) * 3;  // [2,4,3]
        else             p = path + (t - 24) * 3;   // [3,4,3]
        float phi = p[0], th = p[1], om = p[2];
        float ct, st, ca, sa, cb, sb;
        sincosf(0.5f * th, &st, &ct);
        sincosf(0.5f * (phi + om), &sa, &ca);
        sincosf(0.5f * (phi - om), &sb, &cb);
        float* r = g_rot + t * 8;
        r[0] =  ct * ca; r[1] = -ct * sa;   // U00
        r[2] = -st * cb; r[3] = -st * sb;   // U01
        r[4] =  st * cb; r[5] = -st * sb;   // U10
        r[6] =  ct * ca; r[7] =  ct * sa;   // U11
    }
    if (t >= 64 && t < 64 + DOUT) {
        int o = t - 64;
        float m0 = 0, m1 = 0, m2 = 0, m3 = 0, cc = 0;
        for (int j = 0; j < DH; j++) {
            float w = oW[o * DH + j];
            m0 += w * poW[j * NQ + 0];
            m1 += w * poW[j * NQ + 1];
            m2 += w * poW[j * NQ + 2];
            m3 += w * poW[j * NQ + 3];
            cc += w * pob[j];
        }
        g_M[o * NQ + 0] = m0; g_M[o * NQ + 1] = m1;
        g_M[o * NQ + 2] = m2; g_M[o * NQ + 3] = m3;
        g_C[o] = cc + ob[o];
    }
}

// ---------------- CSR build ----------------
__global__ void zero_cnt(int N)
{
    int i = blockIdx.x * blockDim.x + threadIdx.x;
    if (i <= N) g_cnt[i] = 0;
}

__global__ void count_kernel(const int* __restrict__ ei, int E, int N)
{
    int e = blockIdx.x * blockDim.x + threadIdx.x;
    if (e >= E + N) return;
    int dst = (e < E) ? ei[E + e] : (e - E);
    atomicAdd(&g_cnt[dst], 1);
}

__global__ void scan_kernel(int N)
{
    __shared__ int sh[1024];
    __shared__ int carry;
    int tid = threadIdx.x;
    if (tid == 0) carry = 0;
    __syncthreads();
    int chunks = (N + 1023) >> 10;
    for (int c = 0; c < chunks; c++) {
        int i = (c << 10) + tid;
        int v = (i < N) ? g_cnt[i] : 0;
        sh[tid] = v;
        __syncthreads();
        for (int ofs = 1; ofs < 1024; ofs <<= 1) {
            int tmp = (tid >= ofs) ? sh[tid - ofs] : 0;
            __syncthreads();
            sh[tid] += tmp;
            __syncthreads();
        }
        int excl = carry + sh[tid] - v;
        if (i < N) { g_off[i] = excl; g_cur[i] = excl; }
        __syncthreads();
        if (tid == 0) carry += sh[1023];
        __syncthreads();
    }
    if (tid == 0) g_off[N] = carry;
}

__global__ void fill_kernel(const int* __restrict__ ei, int E, int N)
{
    int e = blockIdx.x * blockDim.x + threadIdx.x;
    if (e >= E + N) return;
    int src = (e < E) ? ei[e]     : (e - E);
    int dst = (e < E) ? ei[E + e] : (e - E);
    int pos = atomicAdd(&g_cur[dst], 1);
    g_csr[pos] = make_int2(e, src);
}

// ---------------- SGEMM: C[m,n] = sum_k A[m,k] * W[n,k] + bias[n], N fixed = 128 ----------------
__global__ void gemm128(const float* __restrict__ A, const float* __restrict__ W,
                        const float* __restrict__ bias, float* __restrict__ C,
                        int M, int K, int doRelu)
{
    __shared__ float As[16][68];
    __shared__ float Bs[16][132];
    int tid = threadIdx.x;
    int m0 = blockIdx.x * 64;
    int tx = tid & 31, ty = tid >> 5;
    float acc[8][4];
#pragma unroll
    for (int i = 0; i < 8; i++)
#pragma unroll
        for (int j = 0; j < 4; j++) acc[i][j] = 0.f;

    int ar = tid >> 2, ac = (tid & 3) * 4;
    int br = tid >> 1, bc = (tid & 1) * 8;

    for (int k0 = 0; k0 < K; k0 += 16) {
        float4 av = make_float4(0.f, 0.f, 0.f, 0.f);
        if (m0 + ar < M) av = *(const float4*)(A + (size_t)(m0 + ar) * K + k0 + ac);
        As[ac + 0][ar] = av.x; As[ac + 1][ar] = av.y;
        As[ac + 2][ar] = av.z; As[ac + 3][ar] = av.w;
        float4 b0 = *(const float4*)(W + (size_t)br * K + k0 + bc);
        float4 b1 = *(const float4*)(W + (size_t)br * K + k0 + bc + 4);
        Bs[bc + 0][br] = b0.x; Bs[bc + 1][br] = b0.y;
        Bs[bc + 2][br] = b0.z; Bs[bc + 3][br] = b0.w;
        Bs[bc + 4][br] = b1.x; Bs[bc + 5][br] = b1.y;
        Bs[bc + 6][br] = b1.z; Bs[bc + 7][br] = b1.w;
        __syncthreads();
#pragma unroll
        for (int kk = 0; kk < 16; kk++) {
            float ra[8], rb[4];
#pragma unroll
            for (int i = 0; i < 8; i++) ra[i] = As[kk][ty * 8 + i];
#pragma unroll
            for (int j = 0; j < 4; j++) rb[j] = Bs[kk][tx * 4 + j];
#pragma unroll
            for (int i = 0; i < 8; i++)
#pragma unroll
                for (int j = 0; j < 4; j++) acc[i][j] += ra[i] * rb[j];
        }
        __syncthreads();
    }
#pragma unroll
    for (int i = 0; i < 8; i++) {
        int m = m0 + ty * 8 + i;
        if (m < M) {
#pragma unroll
            for (int j = 0; j < 4; j++) {
                int n = tx * 4 + j;
                float v = acc[i][j] + bias[n];
                if (doRelu) v = fmaxf(v, 0.f);
                C[(size_t)m * DH + n] = v;
            }
        }
    }
}

// ---------------- circuit helpers (16-amp statevector in registers) ----------------
__device__ __forceinline__ void apply_rot(float* ar, float* ai, const float* __restrict__ u, int m)
{
    float u0r = u[0], u0i = u[1], u1r = u[2], u1i = u[3];
    float u2r = u[4], u2i = u[5], u3r = u[6], u3i = u[7];
#pragma unroll
    for (int idx = 0; idx < 16; idx++) {
        if (idx & m) continue;
        int j = idx | m;
        float a0r = ar[idx], a0i = ai[idx], a1r = ar[j], a1i = ai[j];
        ar[idx] = u0r * a0r - u0i * a0i + u1r * a1r - u1i * a1i;
        ai[idx] = u0r * a0i + u0i * a0r + u1r * a1i + u1i * a1r;
        ar[j]   = u2r * a0r - u2i * a0i + u3r * a1r - u3i * a1i;
        ai[j]   = u2r * a0i + u2i * a0r + u3r * a1i + u3i * a1r;
    }
}

__device__ __forceinline__ void cnot_c(float* ar, float* ai, int mc, int mt)
{
#pragma unroll
    for (int idx = 0; idx < 16; idx++) {
        if ((idx & mc) && !(idx & mt)) {
            int j = idx | mt;
            float tr = ar[idx], ti = ai[idx];
            ar[idx] = ar[j]; ai[idx] = ai[j];
            ar[j] = tr;      ai[j] = ti;
        }
    }
}

// ---------------- per-node q/k (two 4x128 matvecs, warp per node) ----------------
__global__ void qk_kernel(const float* __restrict__ h,
                          const float* __restrict__ qW, const float* __restrict__ qb,
                          const float* __restrict__ kW, const float* __restrict__ kb, int N)
{
    int warp = (blockIdx.x * blockDim.x + threadIdx.x) >> 5;
    int lane = threadIdx.x & 31;
    if (warp >= N) return;
    const float* hr = h + (size_t)warp * DH;
    float v0 = hr[lane], v1 = hr[lane + 32], v2 = hr[lane + 64], v3 = hr[lane + 96];
    float acc[8];
#pragma unroll
    for (int i = 0; i < 4; i++) {
        const float* w = qW + i * DH;
        acc[i] = v0 * w[lane] + v1 * w[lane + 32] + v2 * w[lane + 64] + v3 * w[lane + 96];
        const float* w2 = kW + i * DH;
        acc[4 + i] = v0 * w2[lane] + v1 * w2[lane + 32] + v2 * w2[lane + 64] + v3 * w2[lane + 96];
    }
#pragma unroll
    for (int ofs = 16; ofs >= 1; ofs >>= 1)
#pragma unroll
        for (int i = 0; i < 8; i++) acc[i] += __shfl_xor_sync(0xffffffffu, acc[i], ofs);
    if (lane < 4)       g_q[warp * NQ + lane]     = tanhf(acc[lane] + qb[lane]) * PI_HALF;
    else if (lane < 8)  g_k[warp * NQ + lane - 4] = tanhf(acc[lane] + kb[lane - 4]) * PI_HALF;
}

// ---------------- entangle circuit per node ----------------
__global__ void ent_kernel(const float* __restrict__ h, int rotbase, int N)
{
    int n = blockIdx.x * blockDim.x + threadIdx.x;
    if (n >= N) return;
    float cc[4], ss[4];
#pragma unroll
    for (int i = 0; i < 4; i++) {
        float a = tanhf(h[(size_t)n * DH + i]) * PI_HALF;
        sincosf(0.5f * a, &ss[i], &cc[i]);
    }
    float ar[16], ai[16];
#pragma unroll
    for (int idx = 0; idx < 16; idx++) {
        ar[idx] = (idx & 8 ? ss[0] : cc[0]) * (idx & 4 ? ss[1] : cc[1]) *
                  (idx & 2 ? ss[2] : cc[2]) * (idx & 1 ? ss[3] : cc[3]);
        ai[idx] = 0.f;
    }
#pragma unroll
    for (int sub = 0; sub < 2; sub++) {
        cnot_c(ar, ai, 8, 4); cnot_c(ar, ai, 4, 2); cnot_c(ar, ai, 2, 1);
#pragma unroll
        for (int w = 0; w < 4; w++) apply_rot(ar, ai, &g_rot[(rotbase + sub * 4 + w) * 8], 8 >> w);
        cnot_c(ar, ai, 8, 1);
    }
    float z0 = 0, z1 = 0, z2 = 0, z3 = 0;
#pragma unroll
    for (int idx = 0; idx < 16; idx++) {
        float p = ar[idx] * ar[idx] + ai[idx] * ai[idx];
        z0 += (idx & 8) ? -p : p;
        z1 += (idx & 4) ? -p : p;
        z2 += (idx & 2) ? -p : p;
        z3 += (idx & 1) ? -p : p;
    }
    g_xq[n * NQ + 0] = z0; g_xq[n * NQ + 1] = z1;
    g_xq[n * NQ + 2] = z2; g_xq[n * NQ + 3] = z3;
}

// ---------------- x_comb = x_cls + xq @ qproj_W^T + qproj_b (in place on g_xc) ----------------
__global__ void comb_kernel(const float* __restrict__ pW, const float* __restrict__ pb, int N)
{
    int idx = blockIdx.x * blockDim.x + threadIdx.x;
    if (idx >= N * DH) return;
    int n = idx >> 7, j = idx & 127;
    const float* w = pW + j * NQ;
    const float* z = g_xq + n * NQ;
    g_xc[idx] += pb[j] + z[0] * w[0] + z[1] * w[1] + z[2] * w[2] + z[3] * w[3];
}

// ---------------- per-edge attention circuit + exp(score) + partial sums ----------------
__global__ void edge_kernel(const int* __restrict__ ei, int E, int N, int rotbase)
{
    int e = blockIdx.x * blockDim.x + threadIdx.x;
    int E2 = E + N;
    float wgt = 0.f;
    if (e < E2) {
        int src = (e < E) ? ei[e]     : (e - E);
        int dst = (e < E) ? ei[E + e] : (e - E);
        float4 qa = *(const float4*)(g_q + src * NQ);
        float4 ka = *(const float4*)(g_k + dst * NQ);
        float cc[4], ss[4];
        sincosf(0.5f * qa.x, &ss[0], &cc[0]);
        sincosf(0.5f * qa.y, &ss[1], &cc[1]);
        sincosf(0.5f * qa.z, &ss[2], &cc[2]);
        sincosf(0.5f * qa.w, &ss[3], &cc[3]);
        float r[16];
#pragma unroll
        for (int idx = 0; idx < 16; idx++)
            r[idx] = (idx & 8 ? ss[0] : cc[0]) * (idx & 4 ? ss[1] : cc[1]) *
                     (idx & 2 ? ss[2] : cc[2]) * (idx & 1 ? ss[3] : cc[3]);
        // H on every wire (state stays real)
#pragma unroll
        for (int wq = 0; wq < 4; wq++) {
            int m = 8 >> wq;
#pragma unroll
            for (int idx = 0; idx < 16; idx++) {
                if (idx & m) continue;
                int j = idx | m;
                float a = r[idx], b = r[j];
                r[idx] = (a + b) * RSQRT2;
                r[j]   = (a - b) * RSQRT2;
            }
        }
        // CRY(k_i) on (i, (i+1)%4), sequential; still real
        float kang[4] = {ka.x, ka.y, ka.z, ka.w};
#pragma unroll
        for (int i = 0; i < 4; i++) {
            float sc, cs;
            sincosf(0.5f * kang[i], &sc, &cs);
            int mc = 8 >> i, mt = 8 >> ((i + 1) & 3);
#pragma unroll
            for (int idx = 0; idx < 16; idx++) {
                if ((idx & mc) && !(idx & mt)) {
                    int j = idx | mt;
                    float a = r[idx], b = r[j];
                    r[idx] = cs * a - sc * b;
                    r[j]   = sc * a + cs * b;
                }
            }
        }
        // Rot per wire (complexifies)
        float ai[16];
#pragma unroll
        for (int idx = 0; idx < 16; idx++) ai[idx] = 0.f;
#pragma unroll
        for (int wq = 0; wq < 4; wq++) apply_rot(r, ai, &g_rot[(rotbase + wq) * 8], 8 >> wq);
        // mean Z expval = sum p(idx) * (1 - popc(idx)/2)
        float score = 0.f;
#pragma unroll
        for (int idx = 0; idx < 16; idx++) {
            float p = r[idx] * r[idx] + ai[idx] * ai[idx];
            score += p * (1.f - 0.5f * (float)__popc(idx));
        }
        wgt = expf(score);   // scores in [-1,1]: no max-subtraction needed
        g_att[e] = wgt;
    }
    __shared__ float sred[256];
    sred[threadIdx.x] = wgt;
    __syncthreads();
    for (int s = 128; s > 0; s >>= 1) {
        if (threadIdx.x < s) sred[threadIdx.x] += sred[threadIdx.x + s];
        __syncthreads();
    }
    if (threadIdx.x == 0) g_partial[blockIdx.x] = sred[0];
}

__global__ void reduce_kernel(int nb)
{
    __shared__ float s[256];
    float a = 0.f;
    for (int i = threadIdx.x; i < nb; i += 256) a += g_partial[i];
    s[threadIdx.x] = a;
    __syncthreads();
    for (int st = 128; st > 0; st >>= 1) {
        if (threadIdx.x < st) s[threadIdx.x] += s[threadIdx.x + st];
        __syncthreads();
    }
    if (threadIdx.x == 0) g_expsum = s[0];
}

// ---------------- aggregation: h_out[n] = relu( sum_{e in CSR[n]} att[e]/total * x_comb[src[e]] ) ----------------
__global__ void agg_kernel(float* __restrict__ hout, int N)
{
    int n = blockIdx.x;
    int j = threadIdx.x;
    float inv = 1.0f / g_expsum;
    int beg = g_off[n], end = g_off[n + 1];
    float acc = 0.f;
    for (int i = beg; i < end; i++) {
        int2 cs = g_csr[i];
        acc += g_att[cs.x] * g_xc[(size_t)cs.y * DH + j];
    }
    hout[(size_t)n * DH + j] = fmaxf(acc * inv, 0.f);
}

// ---------------- final: pq -> path circuit -> fused output linear (warp per node) ----------------
__global__ void final_kernel(const float* __restrict__ h,
                             const float* __restrict__ piW, const float* __restrict__ pib,
                             float* __restrict__ out, int N)
{
    int warp = (blockIdx.x * blockDim.x + threadIdx.x) >> 5;
    int lane = threadIdx.x & 31;
    if (warp >= N) return;
    const float* hr = h + (size_t)warp * DH;
    float v0 = hr[lane], v1 = hr[lane + 32], v2 = hr[lane + 64], v3 = hr[lane + 96];
    float acc[4];
#pragma unroll
    for (int i = 0; i < 4; i++) {
        const float* w = piW + i * DH;
        acc[i] = v0 * w[lane] + v1 * w[lane + 32] + v2 * w[lane + 64] + v3 * w[lane + 96];
    }
#pragma unroll
    for (int ofs = 16; ofs >= 1; ofs >>= 1)
#pragma unroll
        for (int i = 0; i < 4; i++) acc[i] += __shfl_xor_sync(0xffffffffu, acc[i], ofs);
    float cc[4], ss[4];
#pragma unroll
    for (int i = 0; i < 4; i++) {
        float a = tanhf(acc[i] + pib[i]) * PI_HALF;
        sincosf(0.5f * a, &ss[i], &cc[i]);
    }
    // per-qubit state after H then RY: (c-s)/sqrt2 , (c+s)/sqrt2
    float b0[4], b1[4];
#pragma unroll
    for (int i = 0; i < 4; i++) {
        b0[i] = (cc[i] - ss[i]) * RSQRT2;
        b1[i] = (cc[i] + ss[i]) * RSQRT2;
    }
    float ar[16], ai[16];
#pragma unroll
    for (int idx = 0; idx < 16; idx++) {
        ar[idx] = (idx & 8 ? b1[0] : b0[0]) * (idx & 4 ? b1[1] : b0[1]) *
                  (idx & 2 ? b1[2] : b0[2]) * (idx & 1 ? b1[3] : b0[3]);
        ai[idx] = 0.f;
    }
#pragma unroll
    for (int l = 0; l < 3; l++) {
#pragma unroll
        for (int w = 0; w < 4; w++) apply_rot(ar, ai, &g_rot[(24 + l * 4 + w) * 8], 8 >> w);
        cnot_c(ar, ai, 8, 4); cnot_c(ar, ai, 4, 2); cnot_c(ar, ai, 2, 1);
    }
    float z0 = 0, z1 = 0, z2 = 0, z3 = 0;
#pragma unroll
    for (int idx = 0; idx < 16; idx++) {
        float p = ar[idx] * ar[idx] + ai[idx] * ai[idx];
        z0 += (idx & 8) ? -p : p;
        z1 += (idx & 4) ? -p : p;
        z2 += (idx & 2) ? -p : p;
        z3 += (idx & 1) ? -p : p;
    }
    // out[o] = sum_i z_i * M[o,i] + C[o]  (path_out + out fused)
    out[(size_t)warp * DOUT + lane] =
        z0 * g_M[lane * NQ + 0] + z1 * g_M[lane * NQ + 1] +
        z2 * g_M[lane * NQ + 2] + z3 * g_M[lane * NQ + 3] + g_C[lane];
}

// ---------------- host ----------------
extern "C" void kernel_launch(void* const* d_in, const int* in_sizes, int n_in,
                              void* d_out, int out_size)
{
    const float* x          = (const float*)d_in[0];
    const float* W_in       = (const float*)d_in[1];
    const float* b_in       = (const float*)d_in[2];
    const float* lin_W      = (const float*)d_in[3];
    const float* lin_b      = (const float*)d_in[4];
    const float* qproj_W    = (const float*)d_in[5];
    const float* qproj_b    = (const float*)d_in[6];
    const float* ent_params = (const float*)d_in[7];
    const float* attq_W     = (const float*)d_in[8];
    const float* attq_b     = (const float*)d_in[9];
    const float* attk_W     = (const float*)d_in[10];
    const float* attk_b     = (const float*)d_in[11];
    const float* att_qp     = (const float*)d_in[12];
    const float* path_params= (const float*)d_in[13];
    const float* path_in_W  = (const float*)d_in[14];
    const float* path_in_b  = (const float*)d_in[15];
    const float* path_out_W = (const float*)d_in[16];
    const float* path_out_b = (const float*)d_in[17];
    const float* out_W      = (const float*)d_in[18];
    const float* out_b      = (const float*)d_in[19];
    const int*   edge_index = (const int*)d_in[20];
    float* out = (float*)d_out;

    int N  = in_sizes[0] / DIN;
    int E  = in_sizes[20] / 2;
    int E2 = E + N;

    float *p_h, *p_hn, *p_xc;
    cudaGetSymbolAddress((void**)&p_h,  g_h);
    cudaGetSymbolAddress((void**)&p_hn, g_hn);
    cudaGetSymbolAddress((void**)&p_xc, g_xc);

    int eblocks = (E2 + 255) / 256;

    setup_kernel<<<1, 128>>>(ent_params, att_qp, path_params, path_out_W, path_out_b, out_W, out_b);
    zero_cnt<<<(N + 256) / 256, 256>>>(N);
    count_kernel<<<eblocks, 256>>>(edge_index, E, N);
    scan_kernel<<<1, 1024>>>(N);
    fill_kernel<<<eblocks, 256>>>(edge_index, E, N);

    // h = relu(x @ W_in^T + b_in)
    gemm128<<<(N + 63) / 64, 256>>>(x, W_in, b_in, p_h, N, DIN, 1);

    for (int l = 0; l < 2; l++) {
        const float* hin = (l == 0) ? p_h : p_hn;
        float*       ho  = (l == 0) ? p_hn : p_h;

        gemm128<<<(N + 63) / 64, 256>>>(hin, lin_W + (size_t)l * DH * DH, lin_b + l * DH, p_xc, N, DH, 0);
        qk_kernel<<<(N + 7) / 8, 256>>>(hin, attq_W + (size_t)l * NQ * DH, attq_b + l * NQ,
                                        attk_W + (size_t)l * NQ * DH, attk_b + l * NQ, N);
        ent_kernel<<<(N + 255) / 256, 256>>>(hin, l * 8, N);
        comb_kernel<<<(N * DH + 255) / 256, 256>>>(qproj_W + (size_t)l * DH * NQ, qproj_b + l * DH, N);
        edge_kernel<<<eblocks, 256>>>(edge_index, E, N, 16 + l * 4);
        reduce_kernel<<<1, 256>>>(eblocks);
        agg_kernel<<<N, DH>>>(ho, N);
    }

    final_kernel<<<(N + 7) / 8, 256>>>(p_h, path_in_W, path_in_b, out, N);
}

// round 4
// speedup vs baseline: 1.0740x; 1.0740x over previous
#include <cuda_runtime.h>
#include <math.h>

#define NQ 4
#define DH 128
#define DIN 64
#define DOUT 32
#define PI_HALF 1.5707963267948966f
#define RSQRT2 0.7071067811865476f

#define MAXN 20000
#define MAXE 300000
#define MAXE2 (MAXN + MAXE)

// ---------------- scratch (static device allocations; no cudaMalloc) ----------------
__device__ float g_h[MAXN * DH];
__device__ float g_hn[MAXN * DH];
__device__ float g_xc[MAXN * DH];
__device__ float g_q[MAXN * NQ];
__device__ float g_k[MAXN * NQ];
__device__ float g_xq[MAXN * NQ];
__device__ float g_att[MAXE2];
__device__ float g_partial[4096];
__device__ float g_expsum;
__device__ int   g_cnt[MAXN + 1];
__device__ int   g_off[MAXN + 1];
__device__ int   g_cur[MAXN];
__device__ int   g_bsum[128];
__device__ int2  g_csr[MAXE2];     // .x = edge id, .y = src node
__device__ float g_rot[36 * 8];    // [0..15] ent, [16..23] att, [24..35] path
__device__ float g_M[DOUT * NQ];   // fused path_out -> out
__device__ float g_C[DOUT];

// ---------------- setup: rot matrices + fused output linear ----------------
__global__ void setup_kernel(const float* __restrict__ ent, const float* __restrict__ attqp,
                             const float* __restrict__ path,
                             const float* __restrict__ poW, const float* __restrict__ pob,
                             const float* __restrict__ oW, const float* __restrict__ ob)
{
    int t = threadIdx.x;
    if (t < 36) {
        const float* p;
        if (t < 16)      p = ent + t * 3;
        else if (t < 24) p = attqp + (t - 16) * 3;
        else             p = path + (t - 24) * 3;
        float phi = p[0], th = p[1], om = p[2];
        float ct, st, ca, sa, cb, sb;
        sincosf(0.5f * th, &st, &ct);
        sincosf(0.5f * (phi + om), &sa, &ca);
        sincosf(0.5f * (phi - om), &sb, &cb);
        float* r = g_rot + t * 8;
        r[0] =  ct * ca; r[1] = -ct * sa;   // U00
        r[2] = -st * cb; r[3] = -st * sb;   // U01
        r[4] =  st * cb; r[5] = -st * sb;   // U10
        r[6] =  ct * ca; r[7] =  ct * sa;   // U11
    }
    if (t >= 64 && t < 64 + DOUT) {
        int o = t - 64;
        float m0 = 0, m1 = 0, m2 = 0, m3 = 0, cc = 0;
        for (int j = 0; j < DH; j++) {
            float w = oW[o * DH + j];
            m0 += w * poW[j * NQ + 0];
            m1 += w * poW[j * NQ + 1];
            m2 += w * poW[j * NQ + 2];
            m3 += w * poW[j * NQ + 3];
            cc += w * pob[j];
        }
        g_M[o * NQ + 0] = m0; g_M[o * NQ + 1] = m1;
        g_M[o * NQ + 2] = m2; g_M[o * NQ + 3] = m3;
        g_C[o] = cc + ob[o];
    }
}

// ---------------- CSR build ----------------
__global__ void count_kernel(const int* __restrict__ ei, int E, int N)
{
    int e = blockIdx.x * blockDim.x + threadIdx.x;
    if (e >= E + N) return;
    int dst = (e < E) ? ei[E + e] : (e - E);
    atomicAdd(&g_cnt[dst], 1);
}

// parallel 3-pass exclusive scan of g_cnt[0..N) -> g_off / g_cur
__global__ void scan1_kernel(int N)
{
    __shared__ int wsum[32];
    int i = blockIdx.x * 1024 + threadIdx.x;
    int lane = threadIdx.x & 31, wid = threadIdx.x >> 5;
    int v = (i < N) ? g_cnt[i] : 0;
    int s = v;
#pragma unroll
    for (int o = 1; o < 32; o <<= 1) {
        int t = __shfl_up_sync(0xffffffffu, s, o);
        if (lane >= o) s += t;
    }
    if (lane == 31) wsum[wid] = s;
    __syncthreads();
    if (wid == 0) {
        int ws = wsum[lane];
#pragma unroll
        for (int o = 1; o < 32; o <<= 1) {
            int t = __shfl_up_sync(0xffffffffu, ws, o);
            if (lane >= o) ws += t;
        }
        wsum[lane] = ws;
    }
    __syncthreads();
    int excl = s - v + (wid ? wsum[wid - 1] : 0);
    if (i < N) g_off[i] = excl;
    if (threadIdx.x == 1023) g_bsum[blockIdx.x] = excl + v;
}

__global__ void scan2_kernel(int nb)
{
    if (threadIdx.x == 0) {
        int run = 0;
        for (int b = 0; b < nb; b++) {
            int t = g_bsum[b];
            g_bsum[b] = run;
            run += t;
        }
        g_bsum[nb] = run;
    }
}

__global__ void scan3_kernel(int N, int nb)
{
    int i = blockIdx.x * blockDim.x + threadIdx.x;
    if (i < N) {
        int o = g_off[i] + g_bsum[i >> 10];
        g_off[i] = o;
        g_cur[i] = o;
    }
    if (i == 0) g_off[N] = g_bsum[nb];
}

__global__ void fill_kernel(const int* __restrict__ ei, int E, int N)
{
    int e = blockIdx.x * blockDim.x + threadIdx.x;
    if (e >= E + N) return;
    int src = (e < E) ? ei[e]     : (e - E);
    int dst = (e < E) ? ei[E + e] : (e - E);
    int pos = atomicAdd(&g_cur[dst], 1);
    g_csr[pos] = make_int2(e, src);
}

// ---------------- SGEMM 128x128 tile, 8x8 microkernel, register prefetch ----------------
// C[m,n] = sum_k A[m,k]*W[n,k] + bias[n] (+ optional fused comb: + g_xq[m]·pW[n] + pb[n]) (+relu)
__global__ __launch_bounds__(256, 1)
void gemm128(const float* __restrict__ A, const float* __restrict__ W,
             const float* __restrict__ bias, float* __restrict__ C,
             int M, int K, int doRelu,
             const float* __restrict__ pW, const float* __restrict__ pb)
{
    __shared__ float As[16][128];
    __shared__ float Bs[16][128];
    int tid = threadIdx.x;
    int m0 = blockIdx.x * 128;
    int tx = tid & 15, ty = tid >> 4;

    float acc[8][8];
#pragma unroll
    for (int i = 0; i < 8; i++)
#pragma unroll
        for (int j = 0; j < 8; j++) acc[i][j] = 0.f;

    int lr = tid >> 1;          // 0..127
    int lc = (tid & 1) * 8;     // 0 or 8
    bool mok = (m0 + lr) < M;
    const float* ap = A + (size_t)(m0 + lr) * K + lc;
    const float* bp = W + (size_t)lr * K + lc;

    float4 pa0, pa1, pb0, pb1;
    float4 z4 = make_float4(0.f, 0.f, 0.f, 0.f);
    pa0 = mok ? *(const float4*)(ap)     : z4;
    pa1 = mok ? *(const float4*)(ap + 4) : z4;
    pb0 = *(const float4*)(bp);
    pb1 = *(const float4*)(bp + 4);

    for (int k0 = 0; k0 < K; k0 += 16) {
        __syncthreads();
        As[lc + 0][lr] = pa0.x; As[lc + 1][lr] = pa0.y;
        As[lc + 2][lr] = pa0.z; As[lc + 3][lr] = pa0.w;
        As[lc + 4][lr] = pa1.x; As[lc + 5][lr] = pa1.y;
        As[lc + 6][lr] = pa1.z; As[lc + 7][lr] = pa1.w;
        Bs[lc + 0][lr] = pb0.x; Bs[lc + 1][lr] = pb0.y;
        Bs[lc + 2][lr] = pb0.z; Bs[lc + 3][lr] = pb0.w;
        Bs[lc + 4][lr] = pb1.x; Bs[lc + 5][lr] = pb1.y;
        Bs[lc + 6][lr] = pb1.z; Bs[lc + 7][lr] = pb1.w;
        __syncthreads();
        if (k0 + 16 < K) {
            pa0 = mok ? *(const float4*)(ap + k0 + 16)     : z4;
            pa1 = mok ? *(const float4*)(ap + k0 + 16 + 4) : z4;
            pb0 = *(const float4*)(bp + k0 + 16);
            pb1 = *(const float4*)(bp + k0 + 16 + 4);
        }
#pragma unroll
        for (int kk = 0; kk < 16; kk++) {
            float4 ra0 = *(const float4*)&As[kk][ty * 4];
            float4 ra1 = *(const float4*)&As[kk][64 + ty * 4];
            float4 rb0 = *(const float4*)&Bs[kk][tx * 4];
            float4 rb1 = *(const float4*)&Bs[kk][64 + tx * 4];
            float a[8] = {ra0.x, ra0.y, ra0.z, ra0.w, ra1.x, ra1.y, ra1.z, ra1.w};
            float b[8] = {rb0.x, rb0.y, rb0.z, rb0.w, rb1.x, rb1.y, rb1.z, rb1.w};
#pragma unroll
            for (int i = 0; i < 8; i++)
#pragma unroll
                for (int j = 0; j < 8; j++) acc[i][j] += a[i] * b[j];
        }
    }

    // column metadata (8 cols per thread: tx*4.. and 64+tx*4..)
    float bb[8], pbv[8];
    float4 wcol[8];
#pragma unroll
    for (int j = 0; j < 8; j++) {
        int n = (j < 4) ? (tx * 4 + j) : (64 + tx * 4 + (j - 4));
        bb[j] = bias[n];
        if (pW) { wcol[j] = *(const float4*)(pW + n * NQ); pbv[j] = pb[n]; }
    }
#pragma unroll
    for (int i = 0; i < 8; i++) {
        int m = m0 + ((i < 4) ? (ty * 4 + i) : (64 + ty * 4 + (i - 4)));
        if (m < M) {
            float4 zz = z4;
            if (pW) zz = *(const float4*)(g_xq + m * NQ);
            float o[8];
#pragma unroll
            for (int j = 0; j < 8; j++) {
                float v = acc[i][j] + bb[j];
                if (pW) v += pbv[j] + zz.x * wcol[j].x + zz.y * wcol[j].y
                            + zz.z * wcol[j].z + zz.w * wcol[j].w;
                if (doRelu) v = fmaxf(v, 0.f);
                o[j] = v;
            }
            *(float4*)(C + (size_t)m * DH + tx * 4)      = make_float4(o[0], o[1], o[2], o[3]);
            *(float4*)(C + (size_t)m * DH + 64 + tx * 4) = make_float4(o[4], o[5], o[6], o[7]);
        }
    }
}

// ---------------- circuit helpers (16-amp statevector in registers) ----------------
__device__ __forceinline__ void apply_rot(float* ar, float* ai, const float* __restrict__ u, int m)
{
    float u0r = u[0], u0i = u[1], u1r = u[2], u1i = u[3];
    float u2r = u[4], u2i = u[5], u3r = u[6], u3i = u[7];
#pragma unroll
    for (int idx = 0; idx < 16; idx++) {
        if (idx & m) continue;
        int j = idx | m;
        float a0r = ar[idx], a0i = ai[idx], a1r = ar[j], a1i = ai[j];
        ar[idx] = u0r * a0r - u0i * a0i + u1r * a1r - u1i * a1i;
        ai[idx] = u0r * a0i + u0i * a0r + u1r * a1i + u1i * a1r;
        ar[j]   = u2r * a0r - u2i * a0i + u3r * a1r - u3i * a1i;
        ai[j]   = u2r * a0i + u2i * a0r + u3r * a1i + u3i * a1r;
    }
}

__device__ __forceinline__ void cnot_c(float* ar, float* ai, int mc, int mt)
{
#pragma unroll
    for (int idx = 0; idx < 16; idx++) {
        if ((idx & mc) && !(idx & mt)) {
            int j = idx | mt;
            float tr = ar[idx], ti = ai[idx];
            ar[idx] = ar[j]; ai[idx] = ai[j];
            ar[j] = tr;      ai[j] = ti;
        }
    }
}

// ---------------- per-node q/k (two 4x128 matvecs, warp per node) ----------------
__global__ void qk_kernel(const float* __restrict__ h,
                          const float* __restrict__ qW, const float* __restrict__ qb,
                          const float* __restrict__ kW, const float* __restrict__ kb, int N)
{
    int warp = (blockIdx.x * blockDim.x + threadIdx.x) >> 5;
    int lane = threadIdx.x & 31;
    if (warp >= N) return;
    const float* hr = h + (size_t)warp * DH;
    float v0 = hr[lane], v1 = hr[lane + 32], v2 = hr[lane + 64], v3 = hr[lane + 96];
    float acc[8];
#pragma unroll
    for (int i = 0; i < 4; i++) {
        const float* w = qW + i * DH;
        acc[i] = v0 * w[lane] + v1 * w[lane + 32] + v2 * w[lane + 64] + v3 * w[lane + 96];
        const float* w2 = kW + i * DH;
        acc[4 + i] = v0 * w2[lane] + v1 * w2[lane + 32] + v2 * w2[lane + 64] + v3 * w2[lane + 96];
    }
#pragma unroll
    for (int ofs = 16; ofs >= 1; ofs >>= 1)
#pragma unroll
        for (int i = 0; i < 8; i++) acc[i] += __shfl_xor_sync(0xffffffffu, acc[i], ofs);
    if (lane < 4)       g_q[warp * NQ + lane]     = tanhf(acc[lane] + qb[lane]) * PI_HALF;
    else if (lane < 8)  g_k[warp * NQ + lane - 4] = tanhf(acc[lane] + kb[lane - 4]) * PI_HALF;
}

// ---------------- entangle circuit per node ----------------
__global__ void ent_kernel(const float* __restrict__ h, int rotbase, int N)
{
    int n = blockIdx.x * blockDim.x + threadIdx.x;
    if (n >= N) return;
    float cc[4], ss[4];
#pragma unroll
    for (int i = 0; i < 4; i++) {
        float a = tanhf(h[(size_t)n * DH + i]) * PI_HALF;
        sincosf(0.5f * a, &ss[i], &cc[i]);
    }
    float ar[16], ai[16];
#pragma unroll
    for (int idx = 0; idx < 16; idx++) {
        ar[idx] = (idx & 8 ? ss[0] : cc[0]) * (idx & 4 ? ss[1] : cc[1]) *
                  (idx & 2 ? ss[2] : cc[2]) * (idx & 1 ? ss[3] : cc[3]);
        ai[idx] = 0.f;
    }
#pragma unroll
    for (int sub = 0; sub < 2; sub++) {
        cnot_c(ar, ai, 8, 4); cnot_c(ar, ai, 4, 2); cnot_c(ar, ai, 2, 1);
#pragma unroll
        for (int w = 0; w < 4; w++) apply_rot(ar, ai, &g_rot[(rotbase + sub * 4 + w) * 8], 8 >> w);
        cnot_c(ar, ai, 8, 1);
    }
    float z0 = 0, z1 = 0, z2 = 0, z3 = 0;
#pragma unroll
    for (int idx = 0; idx < 16; idx++) {
        float p = ar[idx] * ar[idx] + ai[idx] * ai[idx];
        z0 += (idx & 8) ? -p : p;
        z1 += (idx & 4) ? -p : p;
        z2 += (idx & 2) ? -p : p;
        z3 += (idx & 1) ? -p : p;
    }
    g_xq[n * NQ + 0] = z0; g_xq[n * NQ + 1] = z1;
    g_xq[n * NQ + 2] = z2; g_xq[n * NQ + 3] = z3;
}

// ---------------- per-edge attention circuit + exp(score) + partial sums ----------------
__global__ void edge_kernel(const int* __restrict__ ei, int E, int N, int rotbase)
{
    int e = blockIdx.x * blockDim.x + threadIdx.x;
    int E2 = E + N;
    float wgt = 0.f;
    if (e < E2) {
        int src = (e < E) ? ei[e]     : (e - E);
        int dst = (e < E) ? ei[E + e] : (e - E);
        float4 qa = *(const float4*)(g_q + src * NQ);
        float4 ka = *(const float4*)(g_k + dst * NQ);
        float cc[4], ss[4];
        sincosf(0.5f * qa.x, &ss[0], &cc[0]);
        sincosf(0.5f * qa.y, &ss[1], &cc[1]);
        sincosf(0.5f * qa.z, &ss[2], &cc[2]);
        sincosf(0.5f * qa.w, &ss[3], &cc[3]);
        float r[16];
#pragma unroll
        for (int idx = 0; idx < 16; idx++)
            r[idx] = (idx & 8 ? ss[0] : cc[0]) * (idx & 4 ? ss[1] : cc[1]) *
                     (idx & 2 ? ss[2] : cc[2]) * (idx & 1 ? ss[3] : cc[3]);
        // H on every wire (state stays real)
#pragma unroll
        for (int wq = 0; wq < 4; wq++) {
            int m = 8 >> wq;
#pragma unroll
            for (int idx = 0; idx < 16; idx++) {
                if (idx & m) continue;
                int j = idx | m;
                float a = r[idx], b = r[j];
                r[idx] = (a + b) * RSQRT2;
                r[j]   = (a - b) * RSQRT2;
            }
        }
        float kang[4] = {ka.x, ka.y, ka.z, ka.w};
#pragma unroll
        for (int i = 0; i < 4; i++) {
            float sc, cs;
            sincosf(0.5f * kang[i], &sc, &cs);
            int mc = 8 >> i, mt = 8 >> ((i + 1) & 3);
#pragma unroll
            for (int idx = 0; idx < 16; idx++) {
                if ((idx & mc) && !(idx & mt)) {
                    int j = idx | mt;
                    float a = r[idx], b = r[j];
                    r[idx] = cs * a - sc * b;
                    r[j]   = sc * a + cs * b;
                }
            }
        }
        float ai[16];
#pragma unroll
        for (int idx = 0; idx < 16; idx++) ai[idx] = 0.f;
#pragma unroll
        for (int wq = 0; wq < 4; wq++) apply_rot(r, ai, &g_rot[(rotbase + wq) * 8], 8 >> wq);
        float score = 0.f;
#pragma unroll
        for (int idx = 0; idx < 16; idx++) {
            float p = r[idx] * r[idx] + ai[idx] * ai[idx];
            score += p * (1.f - 0.5f * (float)__popc(idx));
        }
        wgt = expf(score);
        g_att[e] = wgt;
    }
    __shared__ float sred[256];
    sred[threadIdx.x] = wgt;
    __syncthreads();
    for (int s = 128; s > 0; s >>= 1) {
        if (threadIdx.x < s) sred[threadIdx.x] += sred[threadIdx.x + s];
        __syncthreads();
    }
    if (threadIdx.x == 0) g_partial[blockIdx.x] = sred[0];
}

__global__ void reduce_kernel(int nb)
{
    __shared__ float s[256];
    float a = 0.f;
    for (int i = threadIdx.x; i < nb; i += 256) a += g_partial[i];
    s[threadIdx.x] = a;
    __syncthreads();
    for (int st = 128; st > 0; st >>= 1) {
        if (threadIdx.x < st) s[threadIdx.x] += s[threadIdx.x + st];
        __syncthreads();
    }
    if (threadIdx.x == 0) g_expsum = s[0];
}

// ---------------- aggregation ----------------
__global__ void agg_kernel(float* __restrict__ hout, int N)
{
    int n = blockIdx.x;
    int j = threadIdx.x;
    float inv = 1.0f / g_expsum;
    int beg = g_off[n], end = g_off[n + 1];
    float acc = 0.f;
    for (int i = beg; i < end; i++) {
        int2 cs = g_csr[i];
        acc += g_att[cs.x] * g_xc[(size_t)cs.y * DH + j];
    }
    hout[(size_t)n * DH + j] = fmaxf(acc * inv, 0.f);
}

// ---------------- final: pq -> path circuit -> fused output linear ----------------
__global__ void final_kernel(const float* __restrict__ h,
                             const float* __restrict__ piW, const float* __restrict__ pib,
                             float* __restrict__ out, int N)
{
    int warp = (blockIdx.x * blockDim.x + threadIdx.x) >> 5;
    int lane = threadIdx.x & 31;
    if (warp >= N) return;
    const float* hr = h + (size_t)warp * DH;
    float v0 = hr[lane], v1 = hr[lane + 32], v2 = hr[lane + 64], v3 = hr[lane + 96];
    float acc[4];
#pragma unroll
    for (int i = 0; i < 4; i++) {
        const float* w = piW + i * DH;
        acc[i] = v0 * w[lane] + v1 * w[lane + 32] + v2 * w[lane + 64] + v3 * w[lane + 96];
    }
#pragma unroll
    for (int ofs = 16; ofs >= 1; ofs >>= 1)
#pragma unroll
        for (int i = 0; i < 4; i++) acc[i] += __shfl_xor_sync(0xffffffffu, acc[i], ofs);
    float cc[4], ss[4];
#pragma unroll
    for (int i = 0; i < 4; i++) {
        float a = tanhf(acc[i] + pib[i]) * PI_HALF;
        sincosf(0.5f * a, &ss[i], &cc[i]);
    }
    float b0[4], b1[4];
#pragma unroll
    for (int i = 0; i < 4; i++) {
        b0[i] = (cc[i] - ss[i]) * RSQRT2;
        b1[i] = (cc[i] + ss[i]) * RSQRT2;
    }
    float ar[16], ai[16];
#pragma unroll
    for (int idx = 0; idx < 16; idx++) {
        ar[idx] = (idx & 8 ? b1[0] : b0[0]) * (idx & 4 ? b1[1] : b0[1]) *
                  (idx & 2 ? b1[2] : b0[2]) * (idx & 1 ? b1[3] : b0[3]);
        ai[idx] = 0.f;
    }
#pragma unroll
    for (int l = 0; l < 3; l++) {
#pragma unroll
        for (int w = 0; w < 4; w++) apply_rot(ar, ai, &g_rot[(24 + l * 4 + w) * 8], 8 >> w);
        cnot_c(ar, ai, 8, 4); cnot_c(ar, ai, 4, 2); cnot_c(ar, ai, 2, 1);
    }
    float z0 = 0, z1 = 0, z2 = 0, z3 = 0;
#pragma unroll
    for (int idx = 0; idx < 16; idx++) {
        float p = ar[idx] * ar[idx] + ai[idx] * ai[idx];
        z0 += (idx & 8) ? -p : p;
        z1 += (idx & 4) ? -p : p;
        z2 += (idx & 2) ? -p : p;
        z3 += (idx & 1) ? -p : p;
    }
    out[(size_t)warp * DOUT + lane] =
        z0 * g_M[lane * NQ + 0] + z1 * g_M[lane * NQ + 1] +
        z2 * g_M[lane * NQ + 2] + z3 * g_M[lane * NQ + 3] + g_C[lane];
}

// ---------------- host ----------------
extern "C" void kernel_launch(void* const* d_in, const int* in_sizes, int n_in,
                              void* d_out, int out_size)
{
    const float* x          = (const float*)d_in[0];
    const float* W_in       = (const float*)d_in[1];
    const float* b_in       = (const float*)d_in[2];
    const float* lin_W      = (const float*)d_in[3];
    const float* lin_b      = (const float*)d_in[4];
    const float* qproj_W    = (const float*)d_in[5];
    const float* qproj_b    = (const float*)d_in[6];
    const float* ent_params = (const float*)d_in[7];
    const float* attq_W     = (const float*)d_in[8];
    const float* attq_b     = (const float*)d_in[9];
    const float* attk_W     = (const float*)d_in[10];
    const float* attk_b     = (const float*)d_in[11];
    const float* att_qp     = (const float*)d_in[12];
    const float* path_params= (const float*)d_in[13];
    const float* path_in_W  = (const float*)d_in[14];
    const float* path_in_b  = (const float*)d_in[15];
    const float* path_out_W = (const float*)d_in[16];
    const float* path_out_b = (const float*)d_in[17];
    const float* out_W      = (const float*)d_in[18];
    const float* out_b      = (const float*)d_in[19];
    const int*   edge_index = (const int*)d_in[20];
    float* out = (float*)d_out;

    int N  = in_sizes[0] / DIN;
    int E  = in_sizes[20] / 2;
    int E2 = E + N;

    float *p_h, *p_hn, *p_xc;
    int   *p_cnt;
    cudaGetSymbolAddress((void**)&p_h,   g_h);
    cudaGetSymbolAddress((void**)&p_hn,  g_hn);
    cudaGetSymbolAddress((void**)&p_xc,  g_xc);
    cudaGetSymbolAddress((void**)&p_cnt, g_cnt);

    int eblocks = (E2 + 255) / 256;
    int sblocks = (N + 1023) / 1024;

    setup_kernel<<<1, 128>>>(ent_params, att_qp, path_params, path_out_W, path_out_b, out_W, out_b);
    cudaMemsetAsync(p_cnt, 0, (N + 1) * sizeof(int));
    count_kernel<<<eblocks, 256>>>(edge_index, E, N);
    scan1_kernel<<<sblocks, 1024>>>(N);
    scan2_kernel<<<1, 32>>>(sblocks);
    scan3_kernel<<<(N + 255) / 256, 256>>>(N, sblocks);
    fill_kernel<<<eblocks, 256>>>(edge_index, E, N);

    // h = relu(x @ W_in^T + b_in)
    gemm128<<<(N + 127) / 128, 256>>>(x, W_in, b_in, p_h, N, DIN, 1, nullptr, nullptr);

    for (int l = 0; l < 2; l++) {
        const float* hin = (l == 0) ? p_h : p_hn;
        float*       ho  = (l == 0) ? p_hn : p_h;

        ent_kernel<<<(N + 255) / 256, 256>>>(hin, l * 8, N);
        // x_comb = h@lin_W^T + lin_b + xq@qproj_W^T + qproj_b  (fused epilogue)
        gemm128<<<(N + 127) / 128, 256>>>(hin, lin_W + (size_t)l * DH * DH, lin_b + l * DH,
                                          p_xc, N, DH, 0,
                                          qproj_W + (size_t)l * DH * NQ, qproj_b + l * DH);
        qk_kernel<<<(N + 7) / 8, 256>>>(hin, attq_W + (size_t)l * NQ * DH, attq_b + l * NQ,
                                        attk_W + (size_t)l * NQ * DH, attk_b + l * NQ, N);
        edge_kernel<<<eblocks, 256>>>(edge_index, E, N, 16 + l * 4);
        reduce_kernel<<<1, 256>>>(eblocks);
        agg_kernel<<<N, DH>>>(ho, N);
    }

    final_kernel<<<(N + 7) / 8, 256>>>(p_h, path_in_W, path_in_b, out, N);
}

// round 5
// speedup vs baseline: 1.1906x; 1.1086x over previous
#include <cuda_runtime.h>
#include <math.h>

#define NQ 4
#define DH 128
#define DIN 64
#define DOUT 32
#define PI_HALF 1.5707963267948966f
#define RSQRT2 0.7071067811865476f

#define MAXN 20000
#define MAXE 300000
#define MAXE2 (MAXN + MAXE)

// ---------------- scratch ----------------
__device__ float g_h[MAXN * DH];
__device__ float g_hn[MAXN * DH];
__device__ float g_xc[MAXN * DH];
__device__ float g_qc[MAXN * NQ];   // cos(q/2) per node
__device__ float g_qs[MAXN * NQ];   // sin(q/2)
__device__ float g_kc[MAXN * NQ];   // cos(k/2)
__device__ float g_ks[MAXN * NQ];   // sin(k/2)
__device__ float g_xq[MAXN * NQ];
__device__ float g_att[MAXE2];      // CSR-ordered exp(score)
__device__ int   g_pos[MAXE2];      // edge -> CSR slot
__device__ float g_partial[4096];
__device__ float g_expsum;
__device__ int   g_cnt[MAXN + 1];
__device__ int   g_off[MAXN + 1];
__device__ int   g_cur[MAXN];
__device__ int   g_bsum[128];
__device__ int   g_src[MAXE2];      // CSR-ordered src node
__device__ float g_rot[36 * 8];
__device__ float g_M[DOUT * NQ];
__device__ float g_C[DOUT];

__device__ __forceinline__ float ftanh(float x)
{
    x = fmaxf(fminf(x, 15.f), -15.f);
    float t = __expf(2.f * x);
    return __fdividef(t - 1.f, t + 1.f);
}

// ---------------- setup ----------------
__global__ void setup_kernel(const float* __restrict__ ent, const float* __restrict__ attqp,
                             const float* __restrict__ path,
                             const float* __restrict__ poW, const float* __restrict__ pob,
                             const float* __restrict__ oW, const float* __restrict__ ob)
{
    int t = threadIdx.x;
    if (t < 36) {
        const float* p;
        if (t < 16)      p = ent + t * 3;
        else if (t < 24) p = attqp + (t - 16) * 3;
        else             p = path + (t - 24) * 3;
        float phi = p[0], th = p[1], om = p[2];
        float ct, st, ca, sa, cb, sb;
        sincosf(0.5f * th, &st, &ct);
        sincosf(0.5f * (phi + om), &sa, &ca);
        sincosf(0.5f * (phi - om), &sb, &cb);
        float* r = g_rot + t * 8;
        r[0] =  ct * ca; r[1] = -ct * sa;
        r[2] = -st * cb; r[3] = -st * sb;
        r[4] =  st * cb; r[5] = -st * sb;
        r[6] =  ct * ca; r[7] =  ct * sa;
    }
    if (t >= 64 && t < 64 + DOUT) {
        int o = t - 64;
        float m0 = 0, m1 = 0, m2 = 0, m3 = 0, cc = 0;
        for (int j = 0; j < DH; j++) {
            float w = oW[o * DH + j];
            m0 += w * poW[j * NQ + 0];
            m1 += w * poW[j * NQ + 1];
            m2 += w * poW[j * NQ + 2];
            m3 += w * poW[j * NQ + 3];
            cc += w * pob[j];
        }
        g_M[o * NQ + 0] = m0; g_M[o * NQ + 1] = m1;
        g_M[o * NQ + 2] = m2; g_M[o * NQ + 3] = m3;
        g_C[o] = cc + ob[o];
    }
}

// ---------------- CSR build ----------------
__global__ void count_kernel(const int* __restrict__ ei, int E, int N)
{
    int e = blockIdx.x * blockDim.x + threadIdx.x;
    if (e >= E + N) return;
    int dst = (e < E) ? ei[E + e] : (e - E);
    atomicAdd(&g_cnt[dst], 1);
}

__global__ void scan1_kernel(int N)
{
    __shared__ int wsum[32];
    int i = blockIdx.x * 1024 + threadIdx.x;
    int lane = threadIdx.x & 31, wid = threadIdx.x >> 5;
    int v = (i < N) ? g_cnt[i] : 0;
    int s = v;
#pragma unroll
    for (int o = 1; o < 32; o <<= 1) {
        int t = __shfl_up_sync(0xffffffffu, s, o);
        if (lane >= o) s += t;
    }
    if (lane == 31) wsum[wid] = s;
    __syncthreads();
    if (wid == 0) {
        int ws = wsum[lane];
#pragma unroll
        for (int o = 1; o < 32; o <<= 1) {
            int t = __shfl_up_sync(0xffffffffu, ws, o);
            if (lane >= o) ws += t;
        }
        wsum[lane] = ws;
    }
    __syncthreads();
    int excl = s - v + (wid ? wsum[wid - 1] : 0);
    if (i < N) g_off[i] = excl;
    if (threadIdx.x == 1023) g_bsum[blockIdx.x] = excl + v;
}

__global__ void scan2_kernel(int nb)
{
    int lane = threadIdx.x;
    int v = (lane < nb) ? g_bsum[lane] : 0;
    int s = v;
#pragma unroll
    for (int o = 1; o < 32; o <<= 1) {
        int t = __shfl_up_sync(0xffffffffu, s, o);
        if (lane >= o) s += t;
    }
    if (lane <= nb && lane < 32) g_bsum[lane] = s - v;   // exclusive
    if (lane == 31 || lane == nb - 1) g_bsum[nb] = s;    // total (lane nb-1 has inclusive)
}

__global__ void scan3_kernel(int N, int nb)
{
    int i = blockIdx.x * blockDim.x + threadIdx.x;
    if (i < N) {
        int o = g_off[i] + g_bsum[i >> 10];
        g_off[i] = o;
        g_cur[i] = o;
    }
    if (i == 0) g_off[N] = g_bsum[nb];
}

__global__ void fill_kernel(const int* __restrict__ ei, int E, int N)
{
    int e = blockIdx.x * blockDim.x + threadIdx.x;
    if (e >= E + N) return;
    int src = (e < E) ? ei[e]     : (e - E);
    int dst = (e < E) ? ei[E + e] : (e - E);
    int pos = atomicAdd(&g_cur[dst], 1);
    g_src[pos] = src;
    g_pos[e] = pos;
}

// ---------------- SGEMM 128x128 tile, 8x8 microkernel ----------------
__global__ __launch_bounds__(256, 1)
void gemm128(const float* __restrict__ A, const float* __restrict__ W,
             const float* __restrict__ bias, float* __restrict__ C,
             int M, int K, int doRelu,
             const float* __restrict__ pW, const float* __restrict__ pb)
{
    __shared__ float As[16][128];
    __shared__ float Bs[16][128];
    int tid = threadIdx.x;
    int m0 = blockIdx.x * 128;
    int tx = tid & 15, ty = tid >> 4;

    float acc[8][8];
#pragma unroll
    for (int i = 0; i < 8; i++)
#pragma unroll
        for (int j = 0; j < 8; j++) acc[i][j] = 0.f;

    int lr = tid >> 1;
    int lc = (tid & 1) * 8;
    bool mok = (m0 + lr) < M;
    const float* ap = A + (size_t)(m0 + lr) * K + lc;
    const float* bp = W + (size_t)lr * K + lc;

    float4 pa0, pa1, pb0, pb1;
    float4 z4 = make_float4(0.f, 0.f, 0.f, 0.f);
    pa0 = mok ? *(const float4*)(ap)     : z4;
    pa1 = mok ? *(const float4*)(ap + 4) : z4;
    pb0 = *(const float4*)(bp);
    pb1 = *(const float4*)(bp + 4);

    for (int k0 = 0; k0 < K; k0 += 16) {
        __syncthreads();
        As[lc + 0][lr] = pa0.x; As[lc + 1][lr] = pa0.y;
        As[lc + 2][lr] = pa0.z; As[lc + 3][lr] = pa0.w;
        As[lc + 4][lr] = pa1.x; As[lc + 5][lr] = pa1.y;
        As[lc + 6][lr] = pa1.z; As[lc + 7][lr] = pa1.w;
        Bs[lc + 0][lr] = pb0.x; Bs[lc + 1][lr] = pb0.y;
        Bs[lc + 2][lr] = pb0.z; Bs[lc + 3][lr] = pb0.w;
        Bs[lc + 4][lr] = pb1.x; Bs[lc + 5][lr] = pb1.y;
        Bs[lc + 6][lr] = pb1.z; Bs[lc + 7][lr] = pb1.w;
        __syncthreads();
        if (k0 + 16 < K) {
            pa0 = mok ? *(const float4*)(ap + k0 + 16)     : z4;
            pa1 = mok ? *(const float4*)(ap + k0 + 16 + 4) : z4;
            pb0 = *(const float4*)(bp + k0 + 16);
            pb1 = *(const float4*)(bp + k0 + 16 + 4);
        }
#pragma unroll
        for (int kk = 0; kk < 16; kk++) {
            float4 ra0 = *(const float4*)&As[kk][ty * 4];
            float4 ra1 = *(const float4*)&As[kk][64 + ty * 4];
            float4 rb0 = *(const float4*)&Bs[kk][tx * 4];
            float4 rb1 = *(const float4*)&Bs[kk][64 + tx * 4];
            float a[8] = {ra0.x, ra0.y, ra0.z, ra0.w, ra1.x, ra1.y, ra1.z, ra1.w};
            float b[8] = {rb0.x, rb0.y, rb0.z, rb0.w, rb1.x, rb1.y, rb1.z, rb1.w};
#pragma unroll
            for (int i = 0; i < 8; i++)
#pragma unroll
                for (int j = 0; j < 8; j++) acc[i][j] += a[i] * b[j];
        }
    }

    float bb[8], pbv[8];
    float4 wcol[8];
#pragma unroll
    for (int j = 0; j < 8; j++) {
        int n = (j < 4) ? (tx * 4 + j) : (64 + tx * 4 + (j - 4));
        bb[j] = bias[n];
        if (pW) { wcol[j] = *(const float4*)(pW + n * NQ); pbv[j] = pb[n]; }
    }
#pragma unroll
    for (int i = 0; i < 8; i++) {
        int m = m0 + ((i < 4) ? (ty * 4 + i) : (64 + ty * 4 + (i - 4)));
        if (m < M) {
            float4 zz = z4;
            if (pW) zz = *(const float4*)(g_xq + m * NQ);
            float o[8];
#pragma unroll
            for (int j = 0; j < 8; j++) {
                float v = acc[i][j] + bb[j];
                if (pW) v += pbv[j] + zz.x * wcol[j].x + zz.y * wcol[j].y
                            + zz.z * wcol[j].z + zz.w * wcol[j].w;
                if (doRelu) v = fmaxf(v, 0.f);
                o[j] = v;
            }
            *(float4*)(C + (size_t)m * DH + tx * 4)      = make_float4(o[0], o[1], o[2], o[3]);
            *(float4*)(C + (size_t)m * DH + 64 + tx * 4) = make_float4(o[4], o[5], o[6], o[7]);
        }
    }
}

// ---------------- circuit helpers ----------------
__device__ __forceinline__ void apply_rot(float* ar, float* ai, const float* __restrict__ u, int m)
{
    float u0r = u[0], u0i = u[1], u1r = u[2], u1i = u[3];
    float u2r = u[4], u2i = u[5], u3r = u[6], u3i = u[7];
#pragma unroll
    for (int idx = 0; idx < 16; idx++) {
        if (idx & m) continue;
        int j = idx | m;
        float a0r = ar[idx], a0i = ai[idx], a1r = ar[j], a1i = ai[j];
        ar[idx] = u0r * a0r - u0i * a0i + u1r * a1r - u1i * a1i;
        ai[idx] = u0r * a0i + u0i * a0r + u1r * a1i + u1i * a1r;
        ar[j]   = u2r * a0r - u2i * a0i + u3r * a1r - u3i * a1i;
        ai[j]   = u2r * a0i + u2i * a0r + u3r * a1i + u3i * a1r;
    }
}

__device__ __forceinline__ void cnot_c(float* ar, float* ai, int mc, int mt)
{
#pragma unroll
    for (int idx = 0; idx < 16; idx++) {
        if ((idx & mc) && !(idx & mt)) {
            int j = idx | mt;
            float tr = ar[idx], ti = ai[idx];
            ar[idx] = ar[j]; ai[idx] = ai[j];
            ar[j] = tr;      ai[j] = ti;
        }
    }
}

// ---------------- per-node q/k: matvec + tanh + half-angle sincos ----------------
__global__ void qk_kernel(const float* __restrict__ h,
                          const float* __restrict__ qW, const float* __restrict__ qb,
                          const float* __restrict__ kW, const float* __restrict__ kb, int N)
{
    int warp = (blockIdx.x * blockDim.x + threadIdx.x) >> 5;
    int lane = threadIdx.x & 31;
    if (warp >= N) return;
    const float* hr = h + (size_t)warp * DH;
    float v0 = hr[lane], v1 = hr[lane + 32], v2 = hr[lane + 64], v3 = hr[lane + 96];
    float acc[8];
#pragma unroll
    for (int i = 0; i < 4; i++) {
        const float* w = qW + i * DH;
        acc[i] = v0 * w[lane] + v1 * w[lane + 32] + v2 * w[lane + 64] + v3 * w[lane + 96];
        const float* w2 = kW + i * DH;
        acc[4 + i] = v0 * w2[lane] + v1 * w2[lane + 32] + v2 * w2[lane + 64] + v3 * w2[lane + 96];
    }
#pragma unroll
    for (int ofs = 16; ofs >= 1; ofs >>= 1)
#pragma unroll
        for (int i = 0; i < 8; i++) acc[i] += __shfl_xor_sync(0xffffffffu, acc[i], ofs);
    if (lane < 8) {
        float b = (lane < 4) ? qb[lane] : kb[lane - 4];
        float half = ftanh(acc[lane] + b) * (0.5f * PI_HALF);
        float s, c;
        __sincosf(half, &s, &c);
        if (lane < 4) { g_qc[warp * NQ + lane] = c;     g_qs[warp * NQ + lane] = s; }
        else          { g_kc[warp * NQ + lane - 4] = c; g_ks[warp * NQ + lane - 4] = s; }
    }
}

// ---------------- entangle circuit per node ----------------
__global__ void ent_kernel(const float* __restrict__ h, int rotbase, int N)
{
    int n = blockIdx.x * blockDim.x + threadIdx.x;
    if (n >= N) return;
    float cc[4], ss[4];
#pragma unroll
    for (int i = 0; i < 4; i++) {
        float a = ftanh(h[(size_t)n * DH + i]) * (0.5f * PI_HALF);
        __sincosf(a, &ss[i], &cc[i]);
    }
    float ar[16], ai[16];
#pragma unroll
    for (int idx = 0; idx < 16; idx++) {
        ar[idx] = (idx & 8 ? ss[0] : cc[0]) * (idx & 4 ? ss[1] : cc[1]) *
                  (idx & 2 ? ss[2] : cc[2]) * (idx & 1 ? ss[3] : cc[3]);
        ai[idx] = 0.f;
    }
#pragma unroll
    for (int sub = 0; sub < 2; sub++) {
        cnot_c(ar, ai, 8, 4); cnot_c(ar, ai, 4, 2); cnot_c(ar, ai, 2, 1);
#pragma unroll
        for (int w = 0; w < 4; w++) apply_rot(ar, ai, &g_rot[(rotbase + sub * 4 + w) * 8], 8 >> w);
        cnot_c(ar, ai, 8, 1);
    }
    float z0 = 0, z1 = 0, z2 = 0, z3 = 0;
#pragma unroll
    for (int idx = 0; idx < 16; idx++) {
        float p = ar[idx] * ar[idx] + ai[idx] * ai[idx];
        z0 += (idx & 8) ? -p : p;
        z1 += (idx & 4) ? -p : p;
        z2 += (idx & 2) ? -p : p;
        z3 += (idx & 1) ? -p : p;
    }
    g_xq[n * NQ + 0] = z0; g_xq[n * NQ + 1] = z1;
    g_xq[n * NQ + 2] = z2; g_xq[n * NQ + 3] = z3;
}

// ---------------- per-edge attention circuit (no transcendentals but one __expf) ----------------
__global__ void edge_kernel(const int* __restrict__ ei, int E, int N, int rotbase)
{
    int e = blockIdx.x * blockDim.x + threadIdx.x;
    int E2 = E + N;
    float wgt = 0.f;
    if (e < E2) {
        int src = (e < E) ? ei[e]     : (e - E);
        int dst = (e < E) ? ei[E + e] : (e - E);
        float4 qc = *(const float4*)(g_qc + src * NQ);
        float4 qs = *(const float4*)(g_qs + src * NQ);
        float4 kc = *(const float4*)(g_kc + dst * NQ);
        float4 ks = *(const float4*)(g_ks + dst * NQ);
        float cc[4] = {qc.x, qc.y, qc.z, qc.w};
        float ss[4] = {qs.x, qs.y, qs.z, qs.w};
        float r[16];
#pragma unroll
        for (int idx = 0; idx < 16; idx++)
            r[idx] = (idx & 8 ? ss[0] : cc[0]) * (idx & 4 ? ss[1] : cc[1]) *
                     (idx & 2 ? ss[2] : cc[2]) * (idx & 1 ? ss[3] : cc[3]);
        // H on every wire (state stays real)
#pragma unroll
        for (int wq = 0; wq < 4; wq++) {
            int m = 8 >> wq;
#pragma unroll
            for (int idx = 0; idx < 16; idx++) {
                if (idx & m) continue;
                int j = idx | m;
                float a = r[idx], b = r[j];
                r[idx] = (a + b) * RSQRT2;
                r[j]   = (a - b) * RSQRT2;
            }
        }
        float kcc[4] = {kc.x, kc.y, kc.z, kc.w};
        float kss[4] = {ks.x, ks.y, ks.z, ks.w};
#pragma unroll
        for (int i = 0; i < 4; i++) {
            float cs = kcc[i], sc = kss[i];
            int mc = 8 >> i, mt = 8 >> ((i + 1) & 3);
#pragma unroll
            for (int idx = 0; idx < 16; idx++) {
                if ((idx & mc) && !(idx & mt)) {
                    int j = idx | mt;
                    float a = r[idx], b = r[j];
                    r[idx] = cs * a - sc * b;
                    r[j]   = sc * a + cs * b;
                }
            }
        }
        float ai[16];
#pragma unroll
        for (int idx = 0; idx < 16; idx++) ai[idx] = 0.f;
#pragma unroll
        for (int wq = 0; wq < 4; wq++) apply_rot(r, ai, &g_rot[(rotbase + wq) * 8], 8 >> wq);
        float score = 0.f;
#pragma unroll
        for (int idx = 0; idx < 16; idx++) {
            float p = r[idx] * r[idx] + ai[idx] * ai[idx];
            score += p * (1.f - 0.5f * (float)__popc(idx));
        }
        wgt = __expf(score);
        g_att[g_pos[e]] = wgt;     // write straight into CSR order
    }
    __shared__ float sred[256];
    sred[threadIdx.x] = wgt;
    __syncthreads();
    for (int s = 128; s > 0; s >>= 1) {
        if (threadIdx.x < s) sred[threadIdx.x] += sred[threadIdx.x + s];
        __syncthreads();
    }
    if (threadIdx.x == 0) g_partial[blockIdx.x] = sred[0];
}

__global__ void reduce_kernel(int nb)
{
    __shared__ float s[256];
    float a = 0.f;
    for (int i = threadIdx.x; i < nb; i += 256) a += g_partial[i];
    s[threadIdx.x] = a;
    __syncthreads();
    for (int st = 128; st > 0; st >>= 1) {
        if (threadIdx.x < st) s[threadIdx.x] += s[threadIdx.x + st];
        __syncthreads();
    }
    if (threadIdx.x == 0) g_expsum = s[0];
}

// ---------------- aggregation: warp per node, float4 lanes, 2-edge unroll ----------------
__global__ void agg_kernel(float* __restrict__ hout, int N)
{
    int warp = (blockIdx.x * blockDim.x + threadIdx.x) >> 5;
    int lane = threadIdx.x & 31;
    if (warp >= N) return;
    float inv = __frcp_rn(g_expsum);
    int beg = g_off[warp], end = g_off[warp + 1];
    float4 acc = make_float4(0.f, 0.f, 0.f, 0.f);
    int i = beg;
    for (; i + 1 < end; i += 2) {
        int   s0 = g_src[i],     s1 = g_src[i + 1];
        float w0 = g_att[i],     w1 = g_att[i + 1];
        float4 v0 = *(const float4*)(g_xc + (size_t)s0 * DH + lane * 4);
        float4 v1 = *(const float4*)(g_xc + (size_t)s1 * DH + lane * 4);
        acc.x += w0 * v0.x + w1 * v1.x;
        acc.y += w0 * v0.y + w1 * v1.y;
        acc.z += w0 * v0.z + w1 * v1.z;
        acc.w += w0 * v0.w + w1 * v1.w;
    }
    if (i < end) {
        float w = g_att[i];
        float4 v = *(const float4*)(g_xc + (size_t)g_src[i] * DH + lane * 4);
        acc.x += w * v.x; acc.y += w * v.y; acc.z += w * v.z; acc.w += w * v.w;
    }
    float4 o;
    o.x = fmaxf(acc.x * inv, 0.f);
    o.y = fmaxf(acc.y * inv, 0.f);
    o.z = fmaxf(acc.z * inv, 0.f);
    o.w = fmaxf(acc.w * inv, 0.f);
    *(float4*)(hout + (size_t)warp * DH + lane * 4) = o;
}

// ---------------- final ----------------
__global__ void final_kernel(const float* __restrict__ h,
                             const float* __restrict__ piW, const float* __restrict__ pib,
                             float* __restrict__ out, int N)
{
    int warp = (blockIdx.x * blockDim.x + threadIdx.x) >> 5;
    int lane = threadIdx.x & 31;
    if (warp >= N) return;
    const float* hr = h + (size_t)warp * DH;
    float v0 = hr[lane], v1 = hr[lane + 32], v2 = hr[lane + 64], v3 = hr[lane + 96];
    float acc[4];
#pragma unroll
    for (int i = 0; i < 4; i++) {
        const float* w = piW + i * DH;
        acc[i] = v0 * w[lane] + v1 * w[lane + 32] + v2 * w[lane + 64] + v3 * w[lane + 96];
    }
#pragma unroll
    for (int ofs = 16; ofs >= 1; ofs >>= 1)
#pragma unroll
        for (int i = 0; i < 4; i++) acc[i] += __shfl_xor_sync(0xffffffffu, acc[i], ofs);
    float cc[4], ss[4];
#pragma unroll
    for (int i = 0; i < 4; i++) {
        float a = ftanh(acc[i] + pib[i]) * (0.5f * PI_HALF);
        __sincosf(a, &ss[i], &cc[i]);
    }
    float b0[4], b1[4];
#pragma unroll
    for (int i = 0; i < 4; i++) {
        b0[i] = (cc[i] - ss[i]) * RSQRT2;
        b1[i] = (cc[i] + ss[i]) * RSQRT2;
    }
    float ar[16], ai[16];
#pragma unroll
    for (int idx = 0; idx < 16; idx++) {
        ar[idx] = (idx & 8 ? b1[0] : b0[0]) * (idx & 4 ? b1[1] : b0[1]) *
                  (idx & 2 ? b1[2] : b0[2]) * (idx & 1 ? b1[3] : b0[3]);
        ai[idx] = 0.f;
    }
#pragma unroll
    for (int l = 0; l < 3; l++) {
#pragma unroll
        for (int w = 0; w < 4; w++) apply_rot(ar, ai, &g_rot[(24 + l * 4 + w) * 8], 8 >> w);
        cnot_c(ar, ai, 8, 4); cnot_c(ar, ai, 4, 2); cnot_c(ar, ai, 2, 1);
    }
    float z0 = 0, z1 = 0, z2 = 0, z3 = 0;
#pragma unroll
    for (int idx = 0; idx < 16; idx++) {
        float p = ar[idx] * ar[idx] + ai[idx] * ai[idx];
        z0 += (idx & 8) ? -p : p;
        z1 += (idx & 4) ? -p : p;
        z2 += (idx & 2) ? -p : p;
        z3 += (idx & 1) ? -p : p;
    }
    out[(size_t)warp * DOUT + lane] =
        z0 * g_M[lane * NQ + 0] + z1 * g_M[lane * NQ + 1] +
        z2 * g_M[lane * NQ + 2] + z3 * g_M[lane * NQ + 3] + g_C[lane];
}

// ---------------- host ----------------
extern "C" void kernel_launch(void* const* d_in, const int* in_sizes, int n_in,
                              void* d_out, int out_size)
{
    const float* x          = (const float*)d_in[0];
    const float* W_in       = (const float*)d_in[1];
    const float* b_in       = (const float*)d_in[2];
    const float* lin_W      = (const float*)d_in[3];
    const float* lin_b      = (const float*)d_in[4];
    const float* qproj_W    = (const float*)d_in[5];
    const float* qproj_b    = (const float*)d_in[6];
    const float* ent_params = (const float*)d_in[7];
    const float* attq_W     = (const float*)d_in[8];
    const float* attq_b     = (const float*)d_in[9];
    const float* attk_W     = (const float*)d_in[10];
    const float* attk_b     = (const float*)d_in[11];
    const float* att_qp     = (const float*)d_in[12];
    const float* path_params= (const float*)d_in[13];
    const float* path_in_W  = (const float*)d_in[14];
    const float* path_in_b  = (const float*)d_in[15];
    const float* path_out_W = (const float*)d_in[16];
    const float* path_out_b = (const float*)d_in[17];
    const float* out_W      = (const float*)d_in[18];
    const float* out_b      = (const float*)d_in[19];
    const int*   edge_index = (const int*)d_in[20];
    float* out = (float*)d_out;

    int N  = in_sizes[0] / DIN;
    int E  = in_sizes[20] / 2;
    int E2 = E + N;

    float *p_h, *p_hn, *p_xc;
    int   *p_cnt;
    cudaGetSymbolAddress((void**)&p_h,   g_h);
    cudaGetSymbolAddress((void**)&p_hn,  g_hn);
    cudaGetSymbolAddress((void**)&p_xc,  g_xc);
    cudaGetSymbolAddress((void**)&p_cnt, g_cnt);

    int eblocks = (E2 + 255) / 256;
    int sblocks = (N + 1023) / 1024;

    setup_kernel<<<1, 128>>>(ent_params, att_qp, path_params, path_out_W, path_out_b, out_W, out_b);
    cudaMemsetAsync(p_cnt, 0, (N + 1) * sizeof(int));
    count_kernel<<<eblocks, 256>>>(edge_index, E, N);
    scan1_kernel<<<sblocks, 1024>>>(N);
    scan2_kernel<<<1, 32>>>(sblocks);
    scan3_kernel<<<(N + 255) / 256, 256>>>(N, sblocks);
    fill_kernel<<<eblocks, 256>>>(edge_index, E, N);

    gemm128<<<(N + 127) / 128, 256>>>(x, W_in, b_in, p_h, N, DIN, 1, nullptr, nullptr);

    for (int l = 0; l < 2; l++) {
        const float* hin = (l == 0) ? p_h : p_hn;
        float*       ho  = (l == 0) ? p_hn : p_h;

        ent_kernel<<<(N + 255) / 256, 256>>>(hin, l * 8, N);
        gemm128<<<(N + 127) / 128, 256>>>(hin, lin_W + (size_t)l * DH * DH, lin_b + l * DH,
                                          p_xc, N, DH, 0,
                                          qproj_W + (size_t)l * DH * NQ, qproj_b + l * DH);
        qk_kernel<<<(N + 7) / 8, 256>>>(hin, attq_W + (size_t)l * NQ * DH, attq_b + l * NQ,
                                        attk_W + (size_t)l * NQ * DH, attk_b + l * NQ, N);
        edge_kernel<<<eblocks, 256>>>(edge_index, E, N, 16 + l * 4);
        reduce_kernel<<<1, 256>>>(eblocks);
        agg_kernel<<<(N + 7) / 8, 256>>>(ho, N);
    }

    final_kernel<<<(N + 7) / 8, 256>>>(p_h, path_in_W, path_in_b, out, N);
}

// round 6
// speedup vs baseline: 1.2417x; 1.0429x over previous
#include <cuda_runtime.h>
#include <math.h>

#define NQ 4
#define DH 128
#define DIN 64
#define DOUT 32
#define PI_HALF 1.5707963267948966f
#define RSQRT2 0.7071067811865476f

#define MAXN 20000
#define MAXE 300000
#define MAXE2 (MAXN + MAXE)

// ---------------- scratch ----------------
__device__ float g_h[MAXN * DH];
__device__ float g_hn[MAXN * DH];
__device__ float g_xc[MAXN * DH];
__device__ float g_qtrig[MAXN * 8];   // per node: cos q0..3, sin q0..3
__device__ float g_ktrig[MAXN * 8];   // per node: cos k0..3, sin k0..3
__device__ float g_xq[MAXN * NQ];
__device__ float g_att[MAXE2];        // CSR-ordered exp(score)
__device__ int   g_pos[MAXE2];        // edge -> CSR slot
__device__ float g_partial[4096];
__device__ float g_expsum;
__device__ unsigned g_ctr;            // last-block ticket (maintained at 0)
__device__ int   g_cnt[MAXN + 1];
__device__ int   g_off[MAXN + 1];
__device__ int   g_cur[MAXN];
__device__ int   g_bsum[128];
__device__ int   g_src[MAXE2];        // CSR-ordered src node
__device__ float g_rot[36 * 8];       // [0..15] ent, [24..35] path
__device__ float g_attpre[2 * 40];    // per att layer: ct[16], st[16], ryc[4], rys[4]
__device__ float g_M[DOUT * NQ];
__device__ float g_C[DOUT];

__device__ __forceinline__ float ftanh(float x)
{
    x = fmaxf(fminf(x, 15.f), -15.f);
    float t = __expf(2.f * x);
    return __fdividef(t - 1.f, t + 1.f);
}

// ---------------- setup: rot matrices + att-layer precompute + fused out linear + zero cnt ----------------
__global__ void setup_kernel(const float* __restrict__ ent, const float* __restrict__ attqp,
                             const float* __restrict__ path,
                             const float* __restrict__ poW, const float* __restrict__ pob,
                             const float* __restrict__ oW, const float* __restrict__ ob, int N)
{
    int gi = blockIdx.x * blockDim.x + threadIdx.x;
    if (gi <= N) g_cnt[gi] = 0;
    if (blockIdx.x != 0) return;
    int t = threadIdx.x;
    if (t < 36) {
        const float* p;
        if (t < 16)      p = ent + t * 3;
        else if (t < 24) p = attqp + (t - 16) * 3;
        else             p = path + (t - 24) * 3;
        float phi = p[0], th = p[1], om = p[2];
        float ct, st, ca, sa, cb, sb;
        sincosf(0.5f * th, &st, &ct);
        sincosf(0.5f * (phi + om), &sa, &ca);
        sincosf(0.5f * (phi - om), &sb, &cb);
        float* r = g_rot + t * 8;
        r[0] =  ct * ca; r[1] = -ct * sa;
        r[2] = -st * cb; r[3] = -st * sb;
        r[4] =  st * cb; r[5] = -st * sb;
        r[6] =  ct * ca; r[7] =  ct * sa;
    }
    // att layer precompute: t = 40, 41 -> layers 0, 1
    if (t == 40 || t == 41) {
        int l = t - 40;
        float phi[4], th[4];
        for (int i = 0; i < 4; i++) {
            phi[i] = attqp[l * 12 + i * 3 + 0];
            th[i]  = attqp[l * 12 + i * 3 + 1];
        }
        float* pre = g_attpre + l * 40;
        for (int idx = 0; idx < 16; idx++) {
            float theta = 0.f;
            for (int i = 0; i < 4; i++) {
                int b = (idx >> (3 - i)) & 1;
                theta += 0.5f * (2 * b - 1) * phi[i];
            }
            float s, c;
            sincosf(theta, &s, &c);
            pre[idx] = c; pre[16 + idx] = s;
        }
        for (int i = 0; i < 4; i++) {
            float s, c;
            sincosf(0.5f * th[i], &s, &c);
            pre[32 + i] = c; pre[36 + i] = s;
        }
    }
    if (t >= 64 && t < 64 + DOUT) {
        int o = t - 64;
        float m0 = 0, m1 = 0, m2 = 0, m3 = 0, cc = 0;
        for (int j = 0; j < DH; j++) {
            float w = oW[o * DH + j];
            m0 += w * poW[j * NQ + 0];
            m1 += w * poW[j * NQ + 1];
            m2 += w * poW[j * NQ + 2];
            m3 += w * poW[j * NQ + 3];
            cc += w * pob[j];
        }
        g_M[o * NQ + 0] = m0; g_M[o * NQ + 1] = m1;
        g_M[o * NQ + 2] = m2; g_M[o * NQ + 3] = m3;
        g_C[o] = cc + ob[o];
    }
}

// ---------------- CSR build ----------------
__global__ void count_kernel(const int* __restrict__ ei, int E, int N)
{
    int e = blockIdx.x * blockDim.x + threadIdx.x;
    if (e >= E + N) return;
    int dst = (e < E) ? ei[E + e] : (e - E);
    atomicAdd(&g_cnt[dst], 1);
}

__global__ void scan1_kernel(int N)
{
    __shared__ int wsum[32];
    int i = blockIdx.x * 1024 + threadIdx.x;
    int lane = threadIdx.x & 31, wid = threadIdx.x >> 5;
    int v = (i < N) ? g_cnt[i] : 0;
    int s = v;
#pragma unroll
    for (int o = 1; o < 32; o <<= 1) {
        int t = __shfl_up_sync(0xffffffffu, s, o);
        if (lane >= o) s += t;
    }
    if (lane == 31) wsum[wid] = s;
    __syncthreads();
    if (wid == 0) {
        int ws = wsum[lane];
#pragma unroll
        for (int o = 1; o < 32; o <<= 1) {
            int t = __shfl_up_sync(0xffffffffu, ws, o);
            if (lane >= o) ws += t;
        }
        wsum[lane] = ws;
    }
    __syncthreads();
    int excl = s - v + (wid ? wsum[wid - 1] : 0);
    if (i < N) g_off[i] = excl;
    if (threadIdx.x == 1023) g_bsum[blockIdx.x] = excl + v;
}

// scan3 with inlined block-sum prefix (nb <= 20, cheap per-thread loop; L1 broadcast)
__global__ void scan3_kernel(int N, int nb)
{
    int i = blockIdx.x * blockDim.x + threadIdx.x;
    if (i < N) {
        int blk = i >> 10;
        int base = 0;
        for (int b = 0; b < blk; b++) base += g_bsum[b];
        int o = g_off[i] + base;
        g_off[i] = o;
        g_cur[i] = o;
    }
    if (i == 0) {
        int tot = 0;
        for (int b = 0; b < nb; b++) tot += g_bsum[b];
        g_off[N] = tot;
    }
}

__global__ void fill_kernel(const int* __restrict__ ei, int E, int N)
{
    int e = blockIdx.x * blockDim.x + threadIdx.x;
    if (e >= E + N) return;
    int src = (e < E) ? ei[e]     : (e - E);
    int dst = (e < E) ? ei[E + e] : (e - E);
    int pos = atomicAdd(&g_cur[dst], 1);
    g_src[pos] = src;
    g_pos[e] = pos;
}

// ---------------- SGEMM 64x128 tile, 128 threads, 8x8 microkernel ----------------
__global__ __launch_bounds__(128)
void gemm64(const float* __restrict__ A, const float* __restrict__ W,
            const float* __restrict__ bias, float* __restrict__ C,
            int M, int K, int doRelu,
            const float* __restrict__ pW, const float* __restrict__ pb)
{
    __shared__ float As[16][64];
    __shared__ float Bs[16][128];
    int tid = threadIdx.x;
    int m0 = blockIdx.x * 64;
    int tx = tid & 15, ty = tid >> 4;   // tx: 0..15 cols, ty: 0..7 rows

    float acc[8][8];
#pragma unroll
    for (int i = 0; i < 8; i++)
#pragma unroll
        for (int j = 0; j < 8; j++) acc[i][j] = 0.f;

    int ar = tid >> 1;              // 0..63 (A row)
    int ac = (tid & 1) * 8;         // 0 or 8
    bool mok = (m0 + ar) < M;
    const float* ap = A + (size_t)(m0 + ar) * K + ac;
    const float* bp = W + (size_t)tid * K;   // B row = tid (0..127)

    float4 pa0, pa1, pb0, pb1, pb2, pb3;
    float4 z4 = make_float4(0.f, 0.f, 0.f, 0.f);
    pa0 = mok ? *(const float4*)(ap)     : z4;
    pa1 = mok ? *(const float4*)(ap + 4) : z4;
    pb0 = *(const float4*)(bp + 0);
    pb1 = *(const float4*)(bp + 4);
    pb2 = *(const float4*)(bp + 8);
    pb3 = *(const float4*)(bp + 12);

    for (int k0 = 0; k0 < K; k0 += 16) {
        __syncthreads();
        As[ac + 0][ar] = pa0.x; As[ac + 1][ar] = pa0.y;
        As[ac + 2][ar] = pa0.z; As[ac + 3][ar] = pa0.w;
        As[ac + 4][ar] = pa1.x; As[ac + 5][ar] = pa1.y;
        As[ac + 6][ar] = pa1.z; As[ac + 7][ar] = pa1.w;
        Bs[ 0][tid] = pb0.x; Bs[ 1][tid] = pb0.y; Bs[ 2][tid] = pb0.z; Bs[ 3][tid] = pb0.w;
        Bs[ 4][tid] = pb1.x; Bs[ 5][tid] = pb1.y; Bs[ 6][tid] = pb1.z; Bs[ 7][tid] = pb1.w;
        Bs[ 8][tid] = pb2.x; Bs[ 9][tid] = pb2.y; Bs[10][tid] = pb2.z; Bs[11][tid] = pb2.w;
        Bs[12][tid] = pb3.x; Bs[13][tid] = pb3.y; Bs[14][tid] = pb3.z; Bs[15][tid] = pb3.w;
        __syncthreads();
        if (k0 + 16 < K) {
            pa0 = mok ? *(const float4*)(ap + k0 + 16)     : z4;
            pa1 = mok ? *(const float4*)(ap + k0 + 16 + 4) : z4;
            pb0 = *(const float4*)(bp + k0 + 16);
            pb1 = *(const float4*)(bp + k0 + 20);
            pb2 = *(const float4*)(bp + k0 + 24);
            pb3 = *(const float4*)(bp + k0 + 28);
        }
#pragma unroll
        for (int kk = 0; kk < 16; kk++) {
            float4 ra0 = *(const float4*)&As[kk][ty * 4];
            float4 ra1 = *(const float4*)&As[kk][32 + ty * 4];
            float4 rb0 = *(const float4*)&Bs[kk][tx * 4];
            float4 rb1 = *(const float4*)&Bs[kk][64 + tx * 4];
            float a[8] = {ra0.x, ra0.y, ra0.z, ra0.w, ra1.x, ra1.y, ra1.z, ra1.w};
            float b[8] = {rb0.x, rb0.y, rb0.z, rb0.w, rb1.x, rb1.y, rb1.z, rb1.w};
#pragma unroll
            for (int i = 0; i < 8; i++)
#pragma unroll
                for (int j = 0; j < 8; j++) acc[i][j] += a[i] * b[j];
        }
    }

    float bb[8], pbv[8];
    float4 wcol[8];
#pragma unroll
    for (int j = 0; j < 8; j++) {
        int n = (j < 4) ? (tx * 4 + j) : (64 + tx * 4 + (j - 4));
        bb[j] = bias[n];
        if (pW) { wcol[j] = *(const float4*)(pW + n * NQ); pbv[j] = pb[n]; }
    }
#pragma unroll
    for (int i = 0; i < 8; i++) {
        int m = m0 + ((i < 4) ? (ty * 4 + i) : (32 + ty * 4 + (i - 4)));
        if (m < M) {
            float4 zz = z4;
            if (pW) zz = *(const float4*)(g_xq + m * NQ);
            float o[8];
#pragma unroll
            for (int j = 0; j < 8; j++) {
                float v = acc[i][j] + bb[j];
                if (pW) v += pbv[j] + zz.x * wcol[j].x + zz.y * wcol[j].y
                            + zz.z * wcol[j].z + zz.w * wcol[j].w;
                if (doRelu) v = fmaxf(v, 0.f);
                o[j] = v;
            }
            *(float4*)(C + (size_t)m * DH + tx * 4)      = make_float4(o[0], o[1], o[2], o[3]);
            *(float4*)(C + (size_t)m * DH + 64 + tx * 4) = make_float4(o[4], o[5], o[6], o[7]);
        }
    }
}

// ---------------- circuit helpers ----------------
__device__ __forceinline__ void apply_rot(float* ar, float* ai, const float* __restrict__ u, int m)
{
    float u0r = u[0], u0i = u[1], u1r = u[2], u1i = u[3];
    float u2r = u[4], u2i = u[5], u3r = u[6], u3i = u[7];
#pragma unroll
    for (int idx = 0; idx < 16; idx++) {
        if (idx & m) continue;
        int j = idx | m;
        float a0r = ar[idx], a0i = ai[idx], a1r = ar[j], a1i = ai[j];
        ar[idx] = u0r * a0r - u0i * a0i + u1r * a1r - u1i * a1i;
        ai[idx] = u0r * a0i + u0i * a0r + u1r * a1i + u1i * a1r;
        ar[j]   = u2r * a0r - u2i * a0i + u3r * a1r - u3i * a1i;
        ai[j]   = u2r * a0i + u2i * a0r + u3r * a1i + u3i * a1r;
    }
}

__device__ __forceinline__ void cnot_c(float* ar, float* ai, int mc, int mt)
{
#pragma unroll
    for (int idx = 0; idx < 16; idx++) {
        if ((idx & mc) && !(idx & mt)) {
            int j = idx | mt;
            float tr = ar[idx], ti = ai[idx];
            ar[idx] = ar[j]; ai[idx] = ai[j];
            ar[j] = tr;      ai[j] = ti;
        }
    }
}

// ---------------- per-node q/k ----------------
__global__ void qk_kernel(const float* __restrict__ h,
                          const float* __restrict__ qW, const float* __restrict__ qb,
                          const float* __restrict__ kW, const float* __restrict__ kb, int N)
{
    int warp = (blockIdx.x * blockDim.x + threadIdx.x) >> 5;
    int lane = threadIdx.x & 31;
    if (warp >= N) return;
    const float* hr = h + (size_t)warp * DH;
    float v0 = hr[lane], v1 = hr[lane + 32], v2 = hr[lane + 64], v3 = hr[lane + 96];
    float acc[8];
#pragma unroll
    for (int i = 0; i < 4; i++) {
        const float* w = qW + i * DH;
        acc[i] = v0 * w[lane] + v1 * w[lane + 32] + v2 * w[lane + 64] + v3 * w[lane + 96];
        const float* w2 = kW + i * DH;
        acc[4 + i] = v0 * w2[lane] + v1 * w2[lane + 32] + v2 * w2[lane + 64] + v3 * w2[lane + 96];
    }
#pragma unroll
    for (int ofs = 16; ofs >= 1; ofs >>= 1)
#pragma unroll
        for (int i = 0; i < 8; i++) acc[i] += __shfl_xor_sync(0xffffffffu, acc[i], ofs);
    if (lane < 8) {
        float b = (lane < 4) ? qb[lane] : kb[lane - 4];
        float half = ftanh(acc[lane] + b) * (0.5f * PI_HALF);
        float s, c;
        __sincosf(half, &s, &c);
        if (lane < 4) { g_qtrig[warp * 8 + lane] = c;     g_qtrig[warp * 8 + 4 + lane] = s; }
        else          { g_ktrig[warp * 8 + lane - 4] = c; g_ktrig[warp * 8 + lane] = s; }
    }
}

// ---------------- entangle circuit per node ----------------
__global__ void ent_kernel(const float* __restrict__ h, int rotbase, int N)
{
    int n = blockIdx.x * blockDim.x + threadIdx.x;
    if (n >= N) return;
    float cc[4], ss[4];
#pragma unroll
    for (int i = 0; i < 4; i++) {
        float a = ftanh(h[(size_t)n * DH + i]) * (0.5f * PI_HALF);
        __sincosf(a, &ss[i], &cc[i]);
    }
    float ar[16], ai[16];
#pragma unroll
    for (int idx = 0; idx < 16; idx++) {
        ar[idx] = (idx & 8 ? ss[0] : cc[0]) * (idx & 4 ? ss[1] : cc[1]) *
                  (idx & 2 ? ss[2] : cc[2]) * (idx & 1 ? ss[3] : cc[3]);
        ai[idx] = 0.f;
    }
#pragma unroll
    for (int sub = 0; sub < 2; sub++) {
        cnot_c(ar, ai, 8, 4); cnot_c(ar, ai, 4, 2); cnot_c(ar, ai, 2, 1);
#pragma unroll
        for (int w = 0; w < 4; w++) apply_rot(ar, ai, &g_rot[(rotbase + sub * 4 + w) * 8], 8 >> w);
        cnot_c(ar, ai, 8, 1);
    }
    float z0 = 0, z1 = 0, z2 = 0, z3 = 0;
#pragma unroll
    for (int idx = 0; idx < 16; idx++) {
        float p = ar[idx] * ar[idx] + ai[idx] * ai[idx];
        z0 += (idx & 8) ? -p : p;
        z1 += (idx & 4) ? -p : p;
        z2 += (idx & 2) ? -p : p;
        z3 += (idx & 1) ? -p : p;
    }
    g_xq[n * NQ + 0] = z0; g_xq[n * NQ + 1] = z1;
    g_xq[n * NQ + 2] = z2; g_xq[n * NQ + 3] = z3;
}

// ---------------- per-edge attention circuit; t/u phase trick; last-block exp-sum ----------------
__global__ void edge_kernel(const int* __restrict__ ei, int E, int N, int layer)
{
    __shared__ float pre[40];   // ct[16], st[16], ryc[4], rys[4]
    if (threadIdx.x < 40) pre[threadIdx.x] = g_attpre[layer * 40 + threadIdx.x];
    __syncthreads();

    int e = blockIdx.x * blockDim.x + threadIdx.x;
    int E2 = E + N;
    float wgt = 0.f;
    if (e < E2) {
        int src = (e < E) ? ei[e]     : (e - E);
        int dst = (e < E) ? ei[E + e] : (e - E);
        const float4* qp = (const float4*)(g_qtrig + src * 8);
        const float4* kp = (const float4*)(g_ktrig + dst * 8);
        float4 qc = qp[0], qs = qp[1];
        float4 kc = kp[0], ks = kp[1];
        float cc[4] = {qc.x, qc.y, qc.z, qc.w};
        float ss[4] = {qs.x, qs.y, qs.z, qs.w};
        float r[16];
#pragma unroll
        for (int idx = 0; idx < 16; idx++)
            r[idx] = (idx & 8 ? ss[0] : cc[0]) * (idx & 4 ? ss[1] : cc[1]) *
                     (idx & 2 ? ss[2] : cc[2]) * (idx & 1 ? ss[3] : cc[3]);
        // H on every wire (state stays real)
#pragma unroll
        for (int wq = 0; wq < 4; wq++) {
            int m = 8 >> wq;
#pragma unroll
            for (int idx = 0; idx < 16; idx++) {
                if (idx & m) continue;
                int j = idx | m;
                float a = r[idx], b = r[j];
                r[idx] = (a + b) * RSQRT2;
                r[j]   = (a - b) * RSQRT2;
            }
        }
        float kcc[4] = {kc.x, kc.y, kc.z, kc.w};
        float kss[4] = {ks.x, ks.y, ks.z, ks.w};
#pragma unroll
        for (int i = 0; i < 4; i++) {
            float cs = kcc[i], sc = kss[i];
            int mc = 8 >> i, mt = 8 >> ((i + 1) & 3);
#pragma unroll
            for (int idx = 0; idx < 16; idx++) {
                if ((idx & mc) && !(idx & mt)) {
                    int j = idx | mt;
                    float a = r[idx], b = r[j];
                    r[idx] = cs * a - sc * b;
                    r[j]   = sc * a + cs * b;
                }
            }
        }
        // Rot layer via phase trick: amp_j = r_j * e^{i*theta_j} (theta constant per layer),
        // then real RY per wire on (t,u); omega-RZ dropped (diagonal before measurement).
        float t[16], u[16];
#pragma unroll
        for (int idx = 0; idx < 16; idx++) {
            t[idx] = r[idx] * pre[idx];
            u[idx] = r[idx] * pre[16 + idx];
        }
#pragma unroll
        for (int i = 0; i < 4; i++) {
            float c = pre[32 + i], s = pre[36 + i];
            int m = 8 >> i;
#pragma unroll
            for (int idx = 0; idx < 16; idx++) {
                if (idx & m) continue;
                int j = idx | m;
                float t0 = t[idx], t1 = t[j];
                t[idx] = c * t0 - s * t1;
                t[j]   = s * t0 + c * t1;
                float u0 = u[idx], u1 = u[j];
                u[idx] = c * u0 - s * u1;
                u[j]   = s * u0 + c * u1;
            }
        }
        float score = 0.f;
#pragma unroll
        for (int idx = 0; idx < 16; idx++) {
            float p = t[idx] * t[idx] + u[idx] * u[idx];
            score += p * (1.f - 0.5f * (float)__popc(idx));
        }
        wgt = __expf(score);
        g_att[g_pos[e]] = wgt;
    }
    __shared__ float sred[256];
    sred[threadIdx.x] = wgt;
    __syncthreads();
    for (int s = 128; s > 0; s >>= 1) {
        if (threadIdx.x < s) sred[threadIdx.x] += sred[threadIdx.x + s];
        __syncthreads();
    }
    if (threadIdx.x == 0) g_partial[blockIdx.x] = sred[0];

    // deterministic last-block final reduction
    __shared__ bool amLast;
    __threadfence();
    if (threadIdx.x == 0) {
        unsigned old = atomicAdd(&g_ctr, 1u);
        amLast = (old == gridDim.x - 1);
    }
    __syncthreads();
    if (amLast) {
        float a = 0.f;
        for (int i = threadIdx.x; i < gridDim.x; i += 256) a += g_partial[i];
        sred[threadIdx.x] = a;
        __syncthreads();
        for (int s = 128; s > 0; s >>= 1) {
            if (threadIdx.x < s) sred[threadIdx.x] += sred[threadIdx.x + s];
            __syncthreads();
        }
        if (threadIdx.x == 0) { g_expsum = sred[0]; g_ctr = 0u; }
    }
}

// ---------------- aggregation: warp per node, float4 lanes ----------------
__global__ void agg_kernel(float* __restrict__ hout, int N)
{
    int warp = (blockIdx.x * blockDim.x + threadIdx.x) >> 5;
    int lane = threadIdx.x & 31;
    if (warp >= N) return;
    float inv = __frcp_rn(g_expsum);
    int beg = g_off[warp], end = g_off[warp + 1];
    float4 acc = make_float4(0.f, 0.f, 0.f, 0.f);
    int i = beg;
    for (; i + 1 < end; i += 2) {
        int   s0 = g_src[i],     s1 = g_src[i + 1];
        float w0 = g_att[i],     w1 = g_att[i + 1];
        float4 v0 = *(const float4*)(g_xc + (size_t)s0 * DH + lane * 4);
        float4 v1 = *(const float4*)(g_xc + (size_t)s1 * DH + lane * 4);
        acc.x += w0 * v0.x + w1 * v1.x;
        acc.y += w0 * v0.y + w1 * v1.y;
        acc.z += w0 * v0.z + w1 * v1.z;
        acc.w += w0 * v0.w + w1 * v1.w;
    }
    if (i < end) {
        float w = g_att[i];
        float4 v = *(const float4*)(g_xc + (size_t)g_src[i] * DH + lane * 4);
        acc.x += w * v.x; acc.y += w * v.y; acc.z += w * v.z; acc.w += w * v.w;
    }
    float4 o;
    o.x = fmaxf(acc.x * inv, 0.f);
    o.y = fmaxf(acc.y * inv, 0.f);
    o.z = fmaxf(acc.z * inv, 0.f);
    o.w = fmaxf(acc.w * inv, 0.f);
    *(float4*)(hout + (size_t)warp * DH + lane * 4) = o;
}

// ---------------- final ----------------
__global__ void final_kernel(const float* __restrict__ h,
                             const float* __restrict__ piW, const float* __restrict__ pib,
                             float* __restrict__ out, int N)
{
    int warp = (blockIdx.x * blockDim.x + threadIdx.x) >> 5;
    int lane = threadIdx.x & 31;
    if (warp >= N) return;
    const float* hr = h + (size_t)warp * DH;
    float v0 = hr[lane], v1 = hr[lane + 32], v2 = hr[lane + 64], v3 = hr[lane + 96];
    float acc[4];
#pragma unroll
    for (int i = 0; i < 4; i++) {
        const float* w = piW + i * DH;
        acc[i] = v0 * w[lane] + v1 * w[lane + 32] + v2 * w[lane + 64] + v3 * w[lane + 96];
    }
#pragma unroll
    for (int ofs = 16; ofs >= 1; ofs >>= 1)
#pragma unroll
        for (int i = 0; i < 4; i++) acc[i] += __shfl_xor_sync(0xffffffffu, acc[i], ofs);
    float cc[4], ss[4];
#pragma unroll
    for (int i = 0; i < 4; i++) {
        float a = ftanh(acc[i] + pib[i]) * (0.5f * PI_HALF);
        __sincosf(a, &ss[i], &cc[i]);
    }
    float b0[4], b1[4];
#pragma unroll
    for (int i = 0; i < 4; i++) {
        b0[i] = (cc[i] - ss[i]) * RSQRT2;
        b1[i] = (cc[i] + ss[i]) * RSQRT2;
    }
    float ar[16], ai[16];
#pragma unroll
    for (int idx = 0; idx < 16; idx++) {
        ar[idx] = (idx & 8 ? b1[0] : b0[0]) * (idx & 4 ? b1[1] : b0[1]) *
                  (idx & 2 ? b1[2] : b0[2]) * (idx & 1 ? b1[3] : b0[3]);
        ai[idx] = 0.f;
    }
#pragma unroll
    for (int l = 0; l < 3; l++) {
#pragma unroll
        for (int w = 0; w < 4; w++) apply_rot(ar, ai, &g_rot[(24 + l * 4 + w) * 8], 8 >> w);
        cnot_c(ar, ai, 8, 4); cnot_c(ar, ai, 4, 2); cnot_c(ar, ai, 2, 1);
    }
    float z0 = 0, z1 = 0, z2 = 0, z3 = 0;
#pragma unroll
    for (int idx = 0; idx < 16; idx++) {
        float p = ar[idx] * ar[idx] + ai[idx] * ai[idx];
        z0 += (idx & 8) ? -p : p;
        z1 += (idx & 4) ? -p : p;
        z2 += (idx & 2) ? -p : p;
        z3 += (idx & 1) ? -p : p;
    }
    out[(size_t)warp * DOUT + lane] =
        z0 * g_M[lane * NQ + 0] + z1 * g_M[lane * NQ + 1] +
        z2 * g_M[lane * NQ + 2] + z3 * g_M[lane * NQ + 3] + g_C[lane];
}

// ---------------- host ----------------
extern "C" void kernel_launch(void* const* d_in, const int* in_sizes, int n_in,
                              void* d_out, int out_size)
{
    const float* x          = (const float*)d_in[0];
    const float* W_in       = (const float*)d_in[1];
    const float* b_in       = (const float*)d_in[2];
    const float* lin_W      = (const float*)d_in[3];
    const float* lin_b      = (const float*)d_in[4];
    const float* qproj_W    = (const float*)d_in[5];
    const float* qproj_b    = (const float*)d_in[6];
    const float* ent_params = (const float*)d_in[7];
    const float* attq_W     = (const float*)d_in[8];
    const float* attq_b     = (const float*)d_in[9];
    const float* attk_W     = (const float*)d_in[10];
    const float* attk_b     = (const float*)d_in[11];
    const float* att_qp     = (const float*)d_in[12];
    const float* path_params= (const float*)d_in[13];
    const float* path_in_W  = (const float*)d_in[14];
    const float* path_in_b  = (const float*)d_in[15];
    const float* path_out_W = (const float*)d_in[16];
    const float* path_out_b = (const float*)d_in[17];
    const float* out_W      = (const float*)d_in[18];
    const float* out_b      = (const float*)d_in[19];
    const int*   edge_index = (const int*)d_in[20];
    float* out = (float*)d_out;

    int N  = in_sizes[0] / DIN;
    int E  = in_sizes[20] / 2;
    int E2 = E + N;

    float *p_h, *p_hn, *p_xc;
    cudaGetSymbolAddress((void**)&p_h,  g_h);
    cudaGetSymbolAddress((void**)&p_hn, g_hn);
    cudaGetSymbolAddress((void**)&p_xc, g_xc);

    int eblocks = (E2 + 255) / 256;
    int sblocks = (N + 1023) / 1024;

    setup_kernel<<<(N + 256) / 256, 256>>>(ent_params, att_qp, path_params,
                                           path_out_W, path_out_b, out_W, out_b, N);
    count_kernel<<<eblocks, 256>>>(edge_index, E, N);
    scan1_kernel<<<sblocks, 1024>>>(N);
    scan3_kernel<<<(N + 255) / 256, 256>>>(N, sblocks);
    fill_kernel<<<eblocks, 256>>>(edge_index, E, N);

    gemm64<<<(N + 63) / 64, 128>>>(x, W_in, b_in, p_h, N, DIN, 1, nullptr, nullptr);

    for (int l = 0; l < 2; l++) {
        const float* hin = (l == 0) ? p_h : p_hn;
        float*       ho  = (l == 0) ? p_hn : p_h;

        ent_kernel<<<(N + 255) / 256, 256>>>(hin, l * 8, N);
        gemm64<<<(N + 63) / 64, 128>>>(hin, lin_W + (size_t)l * DH * DH, lin_b + l * DH,
                                       p_xc, N, DH, 0,
                                       qproj_W + (size_t)l * DH * NQ, qproj_b + l * DH);
        qk_kernel<<<(N + 7) / 8, 256>>>(hin, attq_W + (size_t)l * NQ * DH, attq_b + l * NQ,
                                        attk_W + (size_t)l * NQ * DH, attk_b + l * NQ, N);
        edge_kernel<<<eblocks, 256>>>(edge_index, E, N, l);
        agg_kernel<<<(N + 7) / 8, 256>>>(ho, N);
    }

    final_kernel<<<(N + 7) / 8, 256>>>(p_h, path_in_W, path_in_b, out, N);
}

// round 8
// speedup vs baseline: 1.4577x; 1.1740x over previous
#include <cuda_runtime.h>
#include <math.h>

#define NQ 4
#define DH 128
#define DIN 64
#define DOUT 32
#define PI_HALF 1.5707963267948966f
#define RSQRT2 0.7071067811865476f
#define FULL 0xffffffffu

#define MAXN 20000
#define MAXE 300000
#define MAXE2 (MAXN + MAXE)

// ---------------- scratch ----------------
__device__ float g_h[MAXN * DH];
__device__ float g_hn[MAXN * DH];
__device__ float g_xc[MAXN * DH];
__device__ float g_qtrig[MAXN * 8];   // per node: cos q0..3, sin q0..3
__device__ float g_ktrig[MAXN * 8];   // per node: cos k0..3, sin k0..3
__device__ float g_xq[MAXN * NQ];
__device__ float g_att[MAXE2];        // CSR-ordered exp(score)
__device__ int   g_pos[MAXE2];        // edge -> CSR slot
__device__ float g_partial[4096];
__device__ float g_expsum;
__device__ unsigned g_ctr;            // last-block ticket (maintained at 0)
__device__ int   g_cnt[MAXN + 1];
__device__ int   g_off[MAXN + 1];
__device__ int   g_cur[MAXN];
__device__ int   g_chain[64];         // scan lookback chain (value = prefix+1; 0 = not ready)
__device__ int   g_src[MAXE2];        // CSR-ordered src node
__device__ float g_rot[36 * 8];       // [0..15] ent, [24..35] path
__device__ float g_attpre[2 * 40];    // per att layer: ct[16], st[16], ryc[4], rys[4]
__device__ float g_M[DOUT * NQ];
__device__ float g_C[DOUT];

__device__ __forceinline__ float ftanh(float x)
{
    x = fmaxf(fminf(x, 15.f), -15.f);
    float t = __expf(2.f * x);
    return __fdividef(t - 1.f, t + 1.f);
}

// ---------------- setup ----------------
__global__ void setup_kernel(const float* __restrict__ ent, const float* __restrict__ attqp,
                             const float* __restrict__ path,
                             const float* __restrict__ poW, const float* __restrict__ pob,
                             const float* __restrict__ oW, const float* __restrict__ ob, int N)
{
    int gi = blockIdx.x * blockDim.x + threadIdx.x;
    if (gi <= N) g_cnt[gi] = 0;
    if (gi < 64) g_chain[gi] = 0;
    if (blockIdx.x != 0) return;
    int t = threadIdx.x;
    if (t < 36) {
        const float* p;
        if (t < 16)      p = ent + t * 3;
        else if (t < 24) p = attqp + (t - 16) * 3;
        else             p = path + (t - 24) * 3;
        float phi = p[0], th = p[1], om = p[2];
        float ct, st, ca, sa, cb, sb;
        sincosf(0.5f * th, &st, &ct);
        sincosf(0.5f * (phi + om), &sa, &ca);
        sincosf(0.5f * (phi - om), &sb, &cb);
        float* r = g_rot + t * 8;
        r[0] =  ct * ca; r[1] = -ct * sa;
        r[2] = -st * cb; r[3] = -st * sb;
        r[4] =  st * cb; r[5] = -st * sb;
        r[6] =  ct * ca; r[7] =  ct * sa;
    }
    if (t == 40 || t == 41) {
        int l = t - 40;
        float phi[4], th[4];
        for (int i = 0; i < 4; i++) {
            phi[i] = attqp[l * 12 + i * 3 + 0];
            th[i]  = attqp[l * 12 + i * 3 + 1];
        }
        float* pre = g_attpre + l * 40;
        for (int idx = 0; idx < 16; idx++) {
            float theta = 0.f;
            for (int i = 0; i < 4; i++) {
                int b = (idx >> (3 - i)) & 1;
                theta += 0.5f * (2 * b - 1) * phi[i];
            }
            float s, c;
            sincosf(theta, &s, &c);
            pre[idx] = c; pre[16 + idx] = s;
        }
        for (int i = 0; i < 4; i++) {
            float s, c;
            sincosf(0.5f * th[i], &s, &c);
            pre[32 + i] = c; pre[36 + i] = s;
        }
    }
    if (t >= 64 && t < 64 + DOUT) {
        int o = t - 64;
        float m0 = 0, m1 = 0, m2 = 0, m3 = 0, cc = 0;
        for (int j = 0; j < DH; j++) {
            float w = oW[o * DH + j];
            m0 += w * poW[j * NQ + 0];
            m1 += w * poW[j * NQ + 1];
            m2 += w * poW[j * NQ + 2];
            m3 += w * poW[j * NQ + 3];
            cc += w * pob[j];
        }
        g_M[o * NQ + 0] = m0; g_M[o * NQ + 1] = m1;
        g_M[o * NQ + 2] = m2; g_M[o * NQ + 3] = m3;
        g_C[o] = cc + ob[o];
    }
}

// ---------------- CSR build ----------------
__global__ void count_kernel(const int* __restrict__ ei, int E, int N)
{
    int e = blockIdx.x * blockDim.x + threadIdx.x;
    if (e >= E + N) return;
    int dst = (e < E) ? ei[E + e] : (e - E);
    atomicAdd(&g_cnt[dst], 1);
}

// single-kernel exclusive scan with chained lookback (blocks all resident: nb <= 20)
__global__ void scan_kernel(int N, int nb)
{
    __shared__ int wsum[32];
    __shared__ int sbase;
    int b = blockIdx.x;
    int i = b * 1024 + threadIdx.x;
    int lane = threadIdx.x & 31, wid = threadIdx.x >> 5;
    int v = (i < N) ? g_cnt[i] : 0;
    int s = v;
#pragma unroll
    for (int o = 1; o < 32; o <<= 1) {
        int t = __shfl_up_sync(FULL, s, o);
        if (lane >= o) s += t;
    }
    if (lane == 31) wsum[wid] = s;
    __syncthreads();
    if (wid == 0) {
        int ws = wsum[lane];
#pragma unroll
        for (int o = 1; o < 32; o <<= 1) {
            int t = __shfl_up_sync(FULL, ws, o);
            if (lane >= o) ws += t;
        }
        wsum[lane] = ws;
    }
    __syncthreads();
    int excl = s - v + (wid ? wsum[wid - 1] : 0);
    // lookback chain
    if (threadIdx.x == 0) {
        int x;
        if (b == 0) x = 1;
        else { while ((x = *(volatile int*)&g_chain[b - 1]) == 0) {} }
        sbase = x - 1;
    }
    __syncthreads();
    int base = sbase;
    if (i < N) { g_off[i] = base + excl; g_cur[i] = base + excl; }
    if (threadIdx.x == 1023) {
        int tot = base + excl + v;
        *(volatile int*)&g_chain[b] = tot + 1;
        if (b == nb - 1) g_off[N] = tot;
    }
}

__global__ void fill_kernel(const int* __restrict__ ei, int E, int N)
{
    int e = blockIdx.x * blockDim.x + threadIdx.x;
    if (e >= E + N) return;
    int src = (e < E) ? ei[e]     : (e - E);
    int dst = (e < E) ? ei[E + e] : (e - E);
    int pos = atomicAdd(&g_cur[dst], 1);
    g_src[pos] = src;
    g_pos[e] = pos;
}

// ---------------- SGEMM 64x128 tile, 128 threads, 8x8 microkernel ----------------
__global__ __launch_bounds__(128)
void gemm64(const float* __restrict__ A, const float* __restrict__ W,
            const float* __restrict__ bias, float* __restrict__ C,
            int M, int K, int doRelu,
            const float* __restrict__ pW, const float* __restrict__ pb)
{
    __shared__ float As[16][64];
    __shared__ float Bs[16][128];
    int tid = threadIdx.x;
    int m0 = blockIdx.x * 64;
    int tx = tid & 15, ty = tid >> 4;

    float acc[8][8];
#pragma unroll
    for (int i = 0; i < 8; i++)
#pragma unroll
        for (int j = 0; j < 8; j++) acc[i][j] = 0.f;

    int ar = tid >> 1;
    int ac = (tid & 1) * 8;
    bool mok = (m0 + ar) < M;
    const float* ap = A + (size_t)(m0 + ar) * K + ac;
    const float* bp = W + (size_t)tid * K;

    float4 pa0, pa1, pb0, pb1, pb2, pb3;
    float4 z4 = make_float4(0.f, 0.f, 0.f, 0.f);
    pa0 = mok ? *(const float4*)(ap)     : z4;
    pa1 = mok ? *(const float4*)(ap + 4) : z4;
    pb0 = *(const float4*)(bp + 0);
    pb1 = *(const float4*)(bp + 4);
    pb2 = *(const float4*)(bp + 8);
    pb3 = *(const float4*)(bp + 12);

    for (int k0 = 0; k0 < K; k0 += 16) {
        __syncthreads();
        As[ac + 0][ar] = pa0.x; As[ac + 1][ar] = pa0.y;
        As[ac + 2][ar] = pa0.z; As[ac + 3][ar] = pa0.w;
        As[ac + 4][ar] = pa1.x; As[ac + 5][ar] = pa1.y;
        As[ac + 6][ar] = pa1.z; As[ac + 7][ar] = pa1.w;
        Bs[ 0][tid] = pb0.x; Bs[ 1][tid] = pb0.y; Bs[ 2][tid] = pb0.z; Bs[ 3][tid] = pb0.w;
        Bs[ 4][tid] = pb1.x; Bs[ 5][tid] = pb1.y; Bs[ 6][tid] = pb1.z; Bs[ 7][tid] = pb1.w;
        Bs[ 8][tid] = pb2.x; Bs[ 9][tid] = pb2.y; Bs[10][tid] = pb2.z; Bs[11][tid] = pb2.w;
        Bs[12][tid] = pb3.x; Bs[13][tid] = pb3.y; Bs[14][tid] = pb3.z; Bs[15][tid] = pb3.w;
        __syncthreads();
        if (k0 + 16 < K) {
            pa0 = mok ? *(const float4*)(ap + k0 + 16)     : z4;
            pa1 = mok ? *(const float4*)(ap + k0 + 16 + 4) : z4;
            pb0 = *(const float4*)(bp + k0 + 16);
            pb1 = *(const float4*)(bp + k0 + 20);
            pb2 = *(const float4*)(bp + k0 + 24);
            pb3 = *(const float4*)(bp + k0 + 28);
        }
#pragma unroll
        for (int kk = 0; kk < 16; kk++) {
            float4 ra0 = *(const float4*)&As[kk][ty * 4];
            float4 ra1 = *(const float4*)&As[kk][32 + ty * 4];
            float4 rb0 = *(const float4*)&Bs[kk][tx * 4];
            float4 rb1 = *(const float4*)&Bs[kk][64 + tx * 4];
            float a[8] = {ra0.x, ra0.y, ra0.z, ra0.w, ra1.x, ra1.y, ra1.z, ra1.w};
            float b[8] = {rb0.x, rb0.y, rb0.z, rb0.w, rb1.x, rb1.y, rb1.z, rb1.w};
#pragma unroll
            for (int i = 0; i < 8; i++)
#pragma unroll
                for (int j = 0; j < 8; j++) acc[i][j] += a[i] * b[j];
        }
    }

    float bb[8], pbv[8];
    float4 wcol[8];
#pragma unroll
    for (int j = 0; j < 8; j++) {
        int n = (j < 4) ? (tx * 4 + j) : (64 + tx * 4 + (j - 4));
        bb[j] = bias[n];
        if (pW) { wcol[j] = *(const float4*)(pW + n * NQ); pbv[j] = pb[n]; }
    }
#pragma unroll
    for (int i = 0; i < 8; i++) {
        int m = m0 + ((i < 4) ? (ty * 4 + i) : (32 + ty * 4 + (i - 4)));
        if (m < M) {
            float4 zz = z4;
            if (pW) zz = *(const float4*)(g_xq + m * NQ);
            float o[8];
#pragma unroll
            for (int j = 0; j < 8; j++) {
                float v = acc[i][j] + bb[j];
                if (pW) v += pbv[j] + zz.x * wcol[j].x + zz.y * wcol[j].y
                            + zz.z * wcol[j].z + zz.w * wcol[j].w;
                if (doRelu) v = fmaxf(v, 0.f);
                o[j] = v;
            }
            *(float4*)(C + (size_t)m * DH + tx * 4)      = make_float4(o[0], o[1], o[2], o[3]);
            *(float4*)(C + (size_t)m * DH + 64 + tx * 4) = make_float4(o[4], o[5], o[6], o[7]);
        }
    }
}

// ---------------- shuffle-based 16-lane statevector gates (lane L holds amp index L, L<16) ----------------
__device__ __forceinline__ void cnot_shfl(float& ar, float& ai, int L, int mc, int mt)
{
    float pr = __shfl_xor_sync(FULL, ar, mt);
    float pi = __shfl_xor_sync(FULL, ai, mt);
    if (L & mc) { ar = pr; ai = pi; }
}

__device__ __forceinline__ void rot_shfl(float& ar, float& ai, int L, const float* __restrict__ u, int m)
{
    float pr = __shfl_xor_sync(FULL, ar, m);
    float pi = __shfl_xor_sync(FULL, ai, m);
    bool low = !(L & m);
    float owr = low ? u[0] : u[6], owi = low ? u[1] : u[7];   // own coeff
    float par = low ? u[2] : u[4], pai = low ? u[3] : u[5];   // partner coeff
    float nr = owr * ar - owi * ai + par * pr - pai * pi;
    float ni = owr * ai + owi * ar + par * pi + pai * pr;
    ar = nr; ai = ni;
}

// sum p over 16 lanes with Z signs; returns z0..z3 valid on lanes 0..15
__device__ __forceinline__ void zexp_shfl(float ar, float ai, int L,
                                          float& z0, float& z1, float& z2, float& z3)
{
    float p = ar * ar + ai * ai;
    z0 = (L & 8) ? -p : p;
    z1 = (L & 4) ? -p : p;
    z2 = (L & 2) ? -p : p;
    z3 = (L & 1) ? -p : p;
#pragma unroll
    for (int o = 1; o < 16; o <<= 1) {
        z0 += __shfl_xor_sync(FULL, z0, o);
        z1 += __shfl_xor_sync(FULL, z1, o);
        z2 += __shfl_xor_sync(FULL, z2, o);
        z3 += __shfl_xor_sync(FULL, z3, o);
    }
}

// ---------------- fused per-node body: qk matvec + trig, ent circuit ----------------
// hv = this lane's 4 h values (row chunk [lane*4, lane*4+4))
__device__ __forceinline__ void node_body(float4 hv, int n, int lane, int rotbase,
                                          const float* __restrict__ qW, const float* __restrict__ qb,
                                          const float* __restrict__ kW, const float* __restrict__ kb)
{
    // ---- qk matvec (all 32 lanes) ----
    float acc[8];
#pragma unroll
    for (int i = 0; i < 4; i++) {
        float4 wq = *(const float4*)(qW + i * DH + lane * 4);
        acc[i] = hv.x * wq.x + hv.y * wq.y + hv.z * wq.z + hv.w * wq.w;
        float4 wk = *(const float4*)(kW + i * DH + lane * 4);
        acc[4 + i] = hv.x * wk.x + hv.y * wk.y + hv.z * wk.z + hv.w * wk.w;
    }
#pragma unroll
    for (int ofs = 16; ofs >= 1; ofs >>= 1)
#pragma unroll
        for (int i = 0; i < 8; i++) acc[i] += __shfl_xor_sync(FULL, acc[i], ofs);
    if (lane < 8) {
        float b = (lane < 4) ? qb[lane] : kb[lane - 4];
        float half = ftanh(acc[lane] + b) * (0.5f * PI_HALF);
        float s, c;
        __sincosf(half, &s, &c);
        if (lane < 4) { g_qtrig[n * 8 + lane] = c;     g_qtrig[n * 8 + 4 + lane] = s; }
        else          { g_ktrig[n * 8 + lane - 4] = c; g_ktrig[n * 8 + lane] = s; }
    }
    // ---- ent circuit on lanes 0..15 (shfl statevector) ----
    float h0 = __shfl_sync(FULL, hv.x, 0);
    float h1 = __shfl_sync(FULL, hv.y, 0);
    float h2 = __shfl_sync(FULL, hv.z, 0);
    float h3 = __shfl_sync(FULL, hv.w, 0);
    float myc = 1.f, mys = 0.f;
    if (lane < 4) {
        float myh = (lane == 0) ? h0 : (lane == 1) ? h1 : (lane == 2) ? h2 : h3;
        float a = ftanh(myh) * (0.5f * PI_HALF);
        __sincosf(a, &mys, &myc);
    }
    float c0 = __shfl_sync(FULL, myc, 0), s0 = __shfl_sync(FULL, mys, 0);
    float c1 = __shfl_sync(FULL, myc, 1), s1 = __shfl_sync(FULL, mys, 1);
    float c2 = __shfl_sync(FULL, myc, 2), s2 = __shfl_sync(FULL, mys, 2);
    float c3 = __shfl_sync(FULL, myc, 3), s3 = __shfl_sync(FULL, mys, 3);
    int L = lane & 15;
    float ar = (L & 8 ? s0 : c0) * (L & 4 ? s1 : c1) * (L & 2 ? s2 : c2) * (L & 1 ? s3 : c3);
    float ai = 0.f;
#pragma unroll
    for (int sub = 0; sub < 2; sub++) {
        cnot_shfl(ar, ai, L, 8, 4);
        cnot_shfl(ar, ai, L, 4, 2);
        cnot_shfl(ar, ai, L, 2, 1);
#pragma unroll
        for (int w = 0; w < 4; w++)
            rot_shfl(ar, ai, L, &g_rot[(rotbase + sub * 4 + w) * 8], 8 >> w);
        cnot_shfl(ar, ai, L, 8, 1);
    }
    float z0, z1, z2, z3;
    zexp_shfl(ar, ai, L, z0, z1, z2, z3);
    if (lane == 0)
        *(float4*)(g_xq + n * NQ) = make_float4(z0, z1, z2, z3);
}

// ---------------- entqk: warp per node reading h from gmem ----------------
__global__ void entqk_kernel(const float* __restrict__ h, int rotbase,
                             const float* __restrict__ qW, const float* __restrict__ qb,
                             const float* __restrict__ kW, const float* __restrict__ kb, int N)
{
    int warp = (blockIdx.x * blockDim.x + threadIdx.x) >> 5;
    int lane = threadIdx.x & 31;
    if (warp >= N) return;
    float4 hv = *(const float4*)(h + (size_t)warp * DH + lane * 4);
    node_body(hv, warp, lane, rotbase, qW, qb, kW, kb);
}

// ---------------- per-edge attention circuit ----------------
__global__ void edge_kernel(const int* __restrict__ ei, int E, int N, int layer)
{
    __shared__ float pre[40];
    if (threadIdx.x < 40) pre[threadIdx.x] = g_attpre[layer * 40 + threadIdx.x];
    __syncthreads();

    int e = blockIdx.x * blockDim.x + threadIdx.x;
    int E2 = E + N;
    float wgt = 0.f;
    if (e < E2) {
        int src = (e < E) ? ei[e]     : (e - E);
        int dst = (e < E) ? ei[E + e] : (e - E);
        const float4* qp = (const float4*)(g_qtrig + src * 8);
        const float4* kp = (const float4*)(g_ktrig + dst * 8);
        float4 qc = qp[0], qs = qp[1];
        float4 kc = kp[0], ks = kp[1];
        float cc[4] = {qc.x, qc.y, qc.z, qc.w};
        float ss[4] = {qs.x, qs.y, qs.z, qs.w};
        float r[16];
#pragma unroll
        for (int idx = 0; idx < 16; idx++)
            r[idx] = (idx & 8 ? ss[0] : cc[0]) * (idx & 4 ? ss[1] : cc[1]) *
                     (idx & 2 ? ss[2] : cc[2]) * (idx & 1 ? ss[3] : cc[3]);
#pragma unroll
        for (int wq = 0; wq < 4; wq++) {
            int m = 8 >> wq;
#pragma unroll
            for (int idx = 0; idx < 16; idx++) {
                if (idx & m) continue;
                int j = idx | m;
                float a = r[idx], b = r[j];
                r[idx] = (a + b) * RSQRT2;
                r[j]   = (a - b) * RSQRT2;
            }
        }
        float kcc[4] = {kc.x, kc.y, kc.z, kc.w};
        float kss[4] = {ks.x, ks.y, ks.z, ks.w};
#pragma unroll
        for (int i = 0; i < 4; i++) {
            float cs = kcc[i], sc = kss[i];
            int mc = 8 >> i, mt = 8 >> ((i + 1) & 3);
#pragma unroll
            for (int idx = 0; idx < 16; idx++) {
                if ((idx & mc) && !(idx & mt)) {
                    int j = idx | mt;
                    float a = r[idx], b = r[j];
                    r[idx] = cs * a - sc * b;
                    r[j]   = sc * a + cs * b;
                }
            }
        }
        float t[16], u[16];
#pragma unroll
        for (int idx = 0; idx < 16; idx++) {
            t[idx] = r[idx] * pre[idx];
            u[idx] = r[idx] * pre[16 + idx];
        }
#pragma unroll
        for (int i = 0; i < 4; i++) {
            float c = pre[32 + i], s = pre[36 + i];
            int m = 8 >> i;
#pragma unroll
            for (int idx = 0; idx < 16; idx++) {
                if (idx & m) continue;
                int j = idx | m;
                float t0 = t[idx], t1 = t[j];
                t[idx] = c * t0 - s * t1;
                t[j]   = s * t0 + c * t1;
                float u0 = u[idx], u1 = u[j];
                u[idx] = c * u0 - s * u1;
                u[j]   = s * u0 + c * u1;
            }
        }
        float score = 0.f;
#pragma unroll
        for (int idx = 0; idx < 16; idx++) {
            float p = t[idx] * t[idx] + u[idx] * u[idx];
            score += p * (1.f - 0.5f * (float)__popc(idx));
        }
        wgt = __expf(score);
        g_att[g_pos[e]] = wgt;
    }
    __shared__ float sred[256];
    sred[threadIdx.x] = wgt;
    __syncthreads();
    for (int s = 128; s > 0; s >>= 1) {
        if (threadIdx.x < s) sred[threadIdx.x] += sred[threadIdx.x + s];
        __syncthreads();
    }
    if (threadIdx.x == 0) g_partial[blockIdx.x] = sred[0];

    __shared__ bool amLast;
    __threadfence();
    if (threadIdx.x == 0) {
        unsigned old = atomicAdd(&g_ctr, 1u);
        amLast = (old == gridDim.x - 1);
    }
    __syncthreads();
    if (amLast) {
        float a = 0.f;
        for (int i = threadIdx.x; i < gridDim.x; i += 256) a += g_partial[i];
        sred[threadIdx.x] = a;
        __syncthreads();
        for (int s = 128; s > 0; s >>= 1) {
            if (threadIdx.x < s) sred[threadIdx.x] += sred[threadIdx.x + s];
            __syncthreads();
        }
        if (threadIdx.x == 0) { g_expsum = sred[0]; g_ctr = 0u; }
    }
}

// ---------------- agg body: gather-reduce one node's row chunk into float4 ----------------
__device__ __forceinline__ float4 agg_row(int n, int lane)
{
    float inv = __frcp_rn(g_expsum);
    int beg = g_off[n], end = g_off[n + 1];
    float4 acc = make_float4(0.f, 0.f, 0.f, 0.f);
    int i = beg;
    for (; i + 3 < end; i += 4) {
        int   s0 = g_src[i],   s1 = g_src[i+1], s2 = g_src[i+2], s3 = g_src[i+3];
        float w0 = g_att[i],   w1 = g_att[i+1], w2 = g_att[i+2], w3 = g_att[i+3];
        float4 v0 = *(const float4*)(g_xc + (size_t)s0 * DH + lane * 4);
        float4 v1 = *(const float4*)(g_xc + (size_t)s1 * DH + lane * 4);
        float4 v2 = *(const float4*)(g_xc + (size_t)s2 * DH + lane * 4);
        float4 v3 = *(const float4*)(g_xc + (size_t)s3 * DH + lane * 4);
        acc.x += w0*v0.x + w1*v1.x + w2*v2.x + w3*v3.x;
        acc.y += w0*v0.y + w1*v1.y + w2*v2.y + w3*v3.y;
        acc.z += w0*v0.z + w1*v1.z + w2*v2.z + w3*v3.z;
        acc.w += w0*v0.w + w1*v1.w + w2*v2.w + w3*v3.w;
    }
    for (; i < end; i++) {
        float w = g_att[i];
        float4 v = *(const float4*)(g_xc + (size_t)g_src[i] * DH + lane * 4);
        acc.x += w*v.x; acc.y += w*v.y; acc.z += w*v.z; acc.w += w*v.w;
    }
    float4 o;
    o.x = fmaxf(acc.x * inv, 0.f);
    o.y = fmaxf(acc.y * inv, 0.f);
    o.z = fmaxf(acc.z * inv, 0.f);
    o.w = fmaxf(acc.w * inv, 0.f);
    return o;
}

// ---------------- agg + entqk fused (between layers) ----------------
__global__ void aggentqk_kernel(float* __restrict__ hout, int rotbase,
                                const float* __restrict__ qW, const float* __restrict__ qb,
                                const float* __restrict__ kW, const float* __restrict__ kb, int N)
{
    int warp = (blockIdx.x * blockDim.x + threadIdx.x) >> 5;
    int lane = threadIdx.x & 31;
    if (warp >= N) return;
    float4 hv = agg_row(warp, lane);
    *(float4*)(hout + (size_t)warp * DH + lane * 4) = hv;
    node_body(hv, warp, lane, rotbase, qW, qb, kW, kb);
}

// ---------------- agg + final path circuit fused ----------------
__global__ void aggfinal_kernel(const float* __restrict__ piW, const float* __restrict__ pib,
                                float* __restrict__ out, int N)
{
    int warp = (blockIdx.x * blockDim.x + threadIdx.x) >> 5;
    int lane = threadIdx.x & 31;
    if (warp >= N) return;
    float4 hv = agg_row(warp, lane);

    // path_in matvec (4 outputs)
    float acc[4];
#pragma unroll
    for (int i = 0; i < 4; i++) {
        float4 w = *(const float4*)(piW + i * DH + lane * 4);
        acc[i] = hv.x * w.x + hv.y * w.y + hv.z * w.z + hv.w * w.w;
    }
#pragma unroll
    for (int ofs = 16; ofs >= 1; ofs >>= 1)
#pragma unroll
        for (int i = 0; i < 4; i++) acc[i] += __shfl_xor_sync(FULL, acc[i], ofs);

    // lanes 0..3 compute per-wire b0/b1 (H then RY)
    float myb0 = 0.f, myb1 = 0.f;
    if (lane < 4) {
        float a = ftanh(acc[lane] + pib[lane]) * (0.5f * PI_HALF);
        float s, c;
        __sincosf(a, &s, &c);
        myb0 = (c - s) * RSQRT2;
        myb1 = (c + s) * RSQRT2;
    }
    float b00 = __shfl_sync(FULL, myb0, 0), b10 = __shfl_sync(FULL, myb1, 0);
    float b01 = __shfl_sync(FULL, myb0, 1), b11 = __shfl_sync(FULL, myb1, 1);
    float b02 = __shfl_sync(FULL, myb0, 2), b12 = __shfl_sync(FULL, myb1, 2);
    float b03 = __shfl_sync(FULL, myb0, 3), b13 = __shfl_sync(FULL, myb1, 3);
    int L = lane & 15;
    float ar = (L & 8 ? b10 : b00) * (L & 4 ? b11 : b01) * (L & 2 ? b12 : b02) * (L & 1 ? b13 : b03);
    float ai = 0.f;
#pragma unroll
    for (int l = 0; l < 3; l++) {
#pragma unroll
        for (int w = 0; w < 4; w++)
            rot_shfl(ar, ai, L, &g_rot[(24 + l * 4 + w) * 8], 8 >> w);
        cnot_shfl(ar, ai, L, 8, 4);
        cnot_shfl(ar, ai, L, 4, 2);
        cnot_shfl(ar, ai, L, 2, 1);
    }
    float z0, z1, z2, z3;
    zexp_shfl(ar, ai, L, z0, z1, z2, z3);
    z0 = __shfl_sync(FULL, z0, 0);
    z1 = __shfl_sync(FULL, z1, 0);
    z2 = __shfl_sync(FULL, z2, 0);
    z3 = __shfl_sync(FULL, z3, 0);
    float4 m = *(const float4*)(g_M + lane * 4);
    out[(size_t)warp * DOUT + lane] = z0 * m.x + z1 * m.y + z2 * m.z + z3 * m.w + g_C[lane];
}

// ---------------- host ----------------
extern "C" void kernel_launch(void* const* d_in, const int* in_sizes, int n_in,
                              void* d_out, int out_size)
{
    const float* x          = (const float*)d_in[0];
    const float* W_in       = (const float*)d_in[1];
    const float* b_in       = (const float*)d_in[2];
    const float* lin_W      = (const float*)d_in[3];
    const float* lin_b      = (const float*)d_in[4];
    const float* qproj_W    = (const float*)d_in[5];
    const float* qproj_b    = (const float*)d_in[6];
    const float* ent_params = (const float*)d_in[7];
    const float* attq_W     = (const float*)d_in[8];
    const float* attq_b     = (const float*)d_in[9];
    const float* attk_W     = (const float*)d_in[10];
    const float* attk_b     = (const float*)d_in[11];
    const float* att_qp     = (const float*)d_in[12];
    const float* path_params= (const float*)d_in[13];
    const float* path_in_W  = (const float*)d_in[14];
    const float* path_in_b  = (const float*)d_in[15];
    const float* path_out_W = (const float*)d_in[16];
    const float* path_out_b = (const float*)d_in[17];
    const float* out_W      = (const float*)d_in[18];
    const float* out_b      = (const float*)d_in[19];
    const int*   edge_index = (const int*)d_in[20];
    float* out = (float*)d_out;

    int N  = in_sizes[0] / DIN;
    int E  = in_sizes[20] / 2;
    int E2 = E + N;

    float *p_h, *p_hn, *p_xc;
    cudaGetSymbolAddress((void**)&p_h,  g_h);
    cudaGetSymbolAddress((void**)&p_hn, g_hn);
    cudaGetSymbolAddress((void**)&p_xc, g_xc);

    int eblocks = (E2 + 255) / 256;
    int sblocks = (N + 1023) / 1024;

    setup_kernel<<<(N + 256) / 256, 256>>>(ent_params, att_qp, path_params,
                                           path_out_W, path_out_b, out_W, out_b, N);
    count_kernel<<<eblocks, 256>>>(edge_index, E, N);
    scan_kernel<<<sblocks, 1024>>>(N, sblocks);
    fill_kernel<<<eblocks, 256>>>(edge_index, E, N);

    // h0 = relu(x @ W_in^T + b_in)
    gemm64<<<(N + 63) / 64, 128>>>(x, W_in, b_in, p_h, N, DIN, 1, nullptr, nullptr);

    // layer 0: ent+qk from h0
    entqk_kernel<<<(N + 7) / 8, 256>>>(p_h, 0, attq_W, attq_b, attk_W, attk_b, N);
    gemm64<<<(N + 63) / 64, 128>>>(p_h, lin_W, lin_b, p_xc, N, DH, 0, qproj_W, qproj_b);
    edge_kernel<<<eblocks, 256>>>(edge_index, E, N, 0);

    // layer 1: agg -> h1 fused with ent+qk(layer1)
    aggentqk_kernel<<<(N + 7) / 8, 256>>>(p_hn, 8,
                                          attq_W + NQ * DH, attq_b + NQ,
                                          attk_W + NQ * DH, attk_b + NQ, N);
    gemm64<<<(N + 63) / 64, 128>>>(p_hn, lin_W + (size_t)DH * DH, lin_b + DH, p_xc, N, DH, 0,
                                   qproj_W + (size_t)DH * NQ, qproj_b + DH);
    edge_kernel<<<eblocks, 256>>>(edge_index, E, N, 1);

    // final: agg -> path circuit -> out
    aggfinal_kernel<<<(N + 7) / 8, 256>>>(path_in_W, path_in_b, out, N);
}

// round 9
// speedup vs baseline: 1.5101x; 1.0359x over previous
#include <cuda_runtime.h>
#include <math.h>

#define NQ 4
#define DH 128
#define DIN 64
#define DOUT 32
#define PI_HALF 1.5707963267948966f
#define RSQRT2 0.7071067811865476f
#define FULL 0xffffffffu

#define MAXN 20000
#define MAXE 300000
#define MAXE2 (MAXN + MAXE)

// ---------------- scratch ----------------
__device__ float g_h[MAXN * DH];
__device__ float g_hn[MAXN * DH];
__device__ float g_xc[MAXN * DH];
__device__ float g_qtrig[MAXN * 8];   // per node: H-folded q amps a0..3 (bit=0), b0..3 (bit=1)
__device__ float g_ktrig[MAXN * 8];   // per node: cos k0..3, sin k0..3
__device__ float g_xq[MAXN * NQ];
__device__ float g_att[MAXE2];        // CSR-ordered exp(score)
__device__ float g_partial[4096];
__device__ float g_expsum;
__device__ unsigned g_ctr;            // last-block ticket (maintained at 0)
__device__ int   g_cnt[MAXN + 1];
__device__ int   g_off[MAXN + 1];
__device__ int   g_cur[MAXN];
__device__ int   g_chain[64];         // scan lookback chain (value = prefix+1; 0 = not ready)
__device__ int   g_src[MAXE2];        // CSR-ordered src node
__device__ int   g_dst[MAXE2];        // CSR-ordered dst node
__device__ float g_rot[36 * 8];       // [0..15] ent, [24..35] path
__device__ float g_attpre[2 * 8];     // per att layer: wZ[4] = cos(th)/4, wX[4] = sin(th)*cos(phi)/2
__device__ float g_M[DOUT * NQ];
__device__ float g_C[DOUT];

__device__ __forceinline__ float ftanh(float x)
{
    x = fmaxf(fminf(x, 15.f), -15.f);
    float t = __expf(2.f * x);
    return __fdividef(t - 1.f, t + 1.f);
}

// ---------------- setup ----------------
__global__ void setup_kernel(const float* __restrict__ ent, const float* __restrict__ attqp,
                             const float* __restrict__ path,
                             const float* __restrict__ poW, const float* __restrict__ pob,
                             const float* __restrict__ oW, const float* __restrict__ ob, int N)
{
    int gi = blockIdx.x * blockDim.x + threadIdx.x;
    if (gi <= N) g_cnt[gi] = 0;
    if (gi < 64) g_chain[gi] = 0;
    if (blockIdx.x != 0) return;
    int t = threadIdx.x;
    if (t < 36) {
        const float* p;
        if (t < 16)      p = ent + t * 3;
        else if (t < 24) p = attqp + (t - 16) * 3;
        else             p = path + (t - 24) * 3;
        float phi = p[0], th = p[1], om = p[2];
        float ct, st, ca, sa, cb, sb;
        sincosf(0.5f * th, &st, &ct);
        sincosf(0.5f * (phi + om), &sa, &ca);
        sincosf(0.5f * (phi - om), &sb, &cb);
        float* r = g_rot + t * 8;
        r[0] =  ct * ca; r[1] = -ct * sa;
        r[2] = -st * cb; r[3] = -st * sb;
        r[4] =  st * cb; r[5] = -st * sb;
        r[6] =  ct * ca; r[7] =  ct * sa;
    }
    // attention layer observable weights: Rot^dag Z Rot = cos(th) Z - sin(th)(cos(phi) X - sin(phi) Y)
    // real state => <Y> = 0. score = sum_i [ wZ_i * <Z_i> + wX_i * pairsum_i ], pairsum = sum v_j v_{j^m}
    if (t == 40 || t == 41) {
        int l = t - 40;
        float* pre = g_attpre + l * 8;
        for (int i = 0; i < 4; i++) {
            float phi = attqp[l * 12 + i * 3 + 0];
            float th  = attqp[l * 12 + i * 3 + 1];
            float sth, cth;
            sincosf(th, &sth, &cth);
            pre[i]     = 0.25f * cth;
            pre[4 + i] = -0.5f * sth * cosf(phi);
        }
    }
    if (t >= 64 && t < 64 + DOUT) {
        int o = t - 64;
        float m0 = 0, m1 = 0, m2 = 0, m3 = 0, cc = 0;
        for (int j = 0; j < DH; j++) {
            float w = oW[o * DH + j];
            m0 += w * poW[j * NQ + 0];
            m1 += w * poW[j * NQ + 1];
            m2 += w * poW[j * NQ + 2];
            m3 += w * poW[j * NQ + 3];
            cc += w * pob[j];
        }
        g_M[o * NQ + 0] = m0; g_M[o * NQ + 1] = m1;
        g_M[o * NQ + 2] = m2; g_M[o * NQ + 3] = m3;
        g_C[o] = cc + ob[o];
    }
}

// ---------------- CSR build ----------------
__global__ void count_kernel(const int* __restrict__ ei, int E, int N)
{
    int base = (blockIdx.x * blockDim.x + threadIdx.x) * 2;
#pragma unroll
    for (int q = 0; q < 2; q++) {
        int e = base + q;
        if (e < E + N) {
            int dst = (e < E) ? ei[E + e] : (e - E);
            atomicAdd(&g_cnt[dst], 1);
        }
    }
}

// single-kernel exclusive scan with chained lookback (blocks all resident: nb <= 20)
__global__ void scan_kernel(int N, int nb)
{
    __shared__ int wsum[32];
    __shared__ int sbase;
    int b = blockIdx.x;
    int i = b * 1024 + threadIdx.x;
    int lane = threadIdx.x & 31, wid = threadIdx.x >> 5;
    int v = (i < N) ? g_cnt[i] : 0;
    int s = v;
#pragma unroll
    for (int o = 1; o < 32; o <<= 1) {
        int t = __shfl_up_sync(FULL, s, o);
        if (lane >= o) s += t;
    }
    if (lane == 31) wsum[wid] = s;
    __syncthreads();
    if (wid == 0) {
        int ws = wsum[lane];
#pragma unroll
        for (int o = 1; o < 32; o <<= 1) {
            int t = __shfl_up_sync(FULL, ws, o);
            if (lane >= o) ws += t;
        }
        wsum[lane] = ws;
    }
    __syncthreads();
    int excl = s - v + (wid ? wsum[wid - 1] : 0);
    if (threadIdx.x == 0) {
        int x;
        if (b == 0) x = 1;
        else { while ((x = *(volatile int*)&g_chain[b - 1]) == 0) {} }
        sbase = x - 1;
    }
    __syncthreads();
    int base = sbase;
    if (i < N) { g_off[i] = base + excl; g_cur[i] = base + excl; }
    if (threadIdx.x == 1023) {
        int tot = base + excl + v;
        *(volatile int*)&g_chain[b] = tot + 1;
        if (b == nb - 1) g_off[N] = tot;
    }
}

__global__ void fill_kernel(const int* __restrict__ ei, int E, int N)
{
    int base = (blockIdx.x * blockDim.x + threadIdx.x) * 2;
#pragma unroll
    for (int q = 0; q < 2; q++) {
        int e = base + q;
        if (e < E + N) {
            int src = (e < E) ? ei[e]     : (e - E);
            int dst = (e < E) ? ei[E + e] : (e - E);
            int pos = atomicAdd(&g_cur[dst], 1);
            g_src[pos] = src;
            g_dst[pos] = dst;
        }
    }
}

// ---------------- SGEMM 64x128 tile, 128 threads, 8x8 microkernel ----------------
__global__ __launch_bounds__(128)
void gemm64(const float* __restrict__ A, const float* __restrict__ W,
            const float* __restrict__ bias, float* __restrict__ C,
            int M, int K, int doRelu,
            const float* __restrict__ pW, const float* __restrict__ pb)
{
    __shared__ float As[16][64];
    __shared__ float Bs[16][128];
    int tid = threadIdx.x;
    int m0 = blockIdx.x * 64;
    int tx = tid & 15, ty = tid >> 4;

    float acc[8][8];
#pragma unroll
    for (int i = 0; i < 8; i++)
#pragma unroll
        for (int j = 0; j < 8; j++) acc[i][j] = 0.f;

    int ar = tid >> 1;
    int ac = (tid & 1) * 8;
    bool mok = (m0 + ar) < M;
    const float* ap = A + (size_t)(m0 + ar) * K + ac;
    const float* bp = W + (size_t)tid * K;

    float4 pa0, pa1, pb0, pb1, pb2, pb3;
    float4 z4 = make_float4(0.f, 0.f, 0.f, 0.f);
    pa0 = mok ? *(const float4*)(ap)     : z4;
    pa1 = mok ? *(const float4*)(ap + 4) : z4;
    pb0 = *(const float4*)(bp + 0);
    pb1 = *(const float4*)(bp + 4);
    pb2 = *(const float4*)(bp + 8);
    pb3 = *(const float4*)(bp + 12);

    for (int k0 = 0; k0 < K; k0 += 16) {
        __syncthreads();
        As[ac + 0][ar] = pa0.x; As[ac + 1][ar] = pa0.y;
        As[ac + 2][ar] = pa0.z; As[ac + 3][ar] = pa0.w;
        As[ac + 4][ar] = pa1.x; As[ac + 5][ar] = pa1.y;
        As[ac + 6][ar] = pa1.z; As[ac + 7][ar] = pa1.w;
        Bs[ 0][tid] = pb0.x; Bs[ 1][tid] = pb0.y; Bs[ 2][tid] = pb0.z; Bs[ 3][tid] = pb0.w;
        Bs[ 4][tid] = pb1.x; Bs[ 5][tid] = pb1.y; Bs[ 6][tid] = pb1.z; Bs[ 7][tid] = pb1.w;
        Bs[ 8][tid] = pb2.x; Bs[ 9][tid] = pb2.y; Bs[10][tid] = pb2.z; Bs[11][tid] = pb2.w;
        Bs[12][tid] = pb3.x; Bs[13][tid] = pb3.y; Bs[14][tid] = pb3.z; Bs[15][tid] = pb3.w;
        __syncthreads();
        if (k0 + 16 < K) {
            pa0 = mok ? *(const float4*)(ap + k0 + 16)     : z4;
            pa1 = mok ? *(const float4*)(ap + k0 + 16 + 4) : z4;
            pb0 = *(const float4*)(bp + k0 + 16);
            pb1 = *(const float4*)(bp + k0 + 20);
            pb2 = *(const float4*)(bp + k0 + 24);
            pb3 = *(const float4*)(bp + k0 + 28);
        }
#pragma unroll
        for (int kk = 0; kk < 16; kk++) {
            float4 ra0 = *(const float4*)&As[kk][ty * 4];
            float4 ra1 = *(const float4*)&As[kk][32 + ty * 4];
            float4 rb0 = *(const float4*)&Bs[kk][tx * 4];
            float4 rb1 = *(const float4*)&Bs[kk][64 + tx * 4];
            float a[8] = {ra0.x, ra0.y, ra0.z, ra0.w, ra1.x, ra1.y, ra1.z, ra1.w};
            float b[8] = {rb0.x, rb0.y, rb0.z, rb0.w, rb1.x, rb1.y, rb1.z, rb1.w};
#pragma unroll
            for (int i = 0; i < 8; i++)
#pragma unroll
                for (int j = 0; j < 8; j++) acc[i][j] += a[i] * b[j];
        }
    }

    float bb[8], pbv[8];
    float4 wcol[8];
#pragma unroll
    for (int j = 0; j < 8; j++) {
        int n = (j < 4) ? (tx * 4 + j) : (64 + tx * 4 + (j - 4));
        bb[j] = bias[n];
        if (pW) { wcol[j] = *(const float4*)(pW + n * NQ); pbv[j] = pb[n]; }
    }
#pragma unroll
    for (int i = 0; i < 8; i++) {
        int m = m0 + ((i < 4) ? (ty * 4 + i) : (32 + ty * 4 + (i - 4)));
        if (m < M) {
            float4 zz = z4;
            if (pW) zz = *(const float4*)(g_xq + m * NQ);
            float o[8];
#pragma unroll
            for (int j = 0; j < 8; j++) {
                float v = acc[i][j] + bb[j];
                if (pW) v += pbv[j] + zz.x * wcol[j].x + zz.y * wcol[j].y
                            + zz.z * wcol[j].z + zz.w * wcol[j].w;
                if (doRelu) v = fmaxf(v, 0.f);
                o[j] = v;
            }
            *(float4*)(C + (size_t)m * DH + tx * 4)      = make_float4(o[0], o[1], o[2], o[3]);
            *(float4*)(C + (size_t)m * DH + 64 + tx * 4) = make_float4(o[4], o[5], o[6], o[7]);
        }
    }
}

// ---------------- shuffle-based 16-lane statevector gates ----------------
__device__ __forceinline__ void cnot_shfl(float& ar, float& ai, int L, int mc, int mt)
{
    float pr = __shfl_xor_sync(FULL, ar, mt);
    float pi = __shfl_xor_sync(FULL, ai, mt);
    if (L & mc) { ar = pr; ai = pi; }
}

__device__ __forceinline__ void rot_shfl(float& ar, float& ai, int L, const float* __restrict__ u, int m)
{
    float pr = __shfl_xor_sync(FULL, ar, m);
    float pi = __shfl_xor_sync(FULL, ai, m);
    bool low = !(L & m);
    float owr = low ? u[0] : u[6], owi = low ? u[1] : u[7];
    float par = low ? u[2] : u[4], pai = low ? u[3] : u[5];
    float nr = owr * ar - owi * ai + par * pr - pai * pi;
    float ni = owr * ai + owi * ar + par * pi + pai * pr;
    ar = nr; ai = ni;
}

__device__ __forceinline__ void zexp_shfl(float ar, float ai, int L,
                                          float& z0, float& z1, float& z2, float& z3)
{
    float p = ar * ar + ai * ai;
    z0 = (L & 8) ? -p : p;
    z1 = (L & 4) ? -p : p;
    z2 = (L & 2) ? -p : p;
    z3 = (L & 1) ? -p : p;
#pragma unroll
    for (int o = 1; o < 16; o <<= 1) {
        z0 += __shfl_xor_sync(FULL, z0, o);
        z1 += __shfl_xor_sync(FULL, z1, o);
        z2 += __shfl_xor_sync(FULL, z2, o);
        z3 += __shfl_xor_sync(FULL, z3, o);
    }
}

// ---------------- fused per-node body: qk matvec + trig, ent circuit ----------------
__device__ __forceinline__ void node_body(float4 hv, int n, int lane, int rotbase,
                                          const float* __restrict__ qW, const float* __restrict__ qb,
                                          const float* __restrict__ kW, const float* __restrict__ kb)
{
    float acc[8];
#pragma unroll
    for (int i = 0; i < 4; i++) {
        float4 wq = *(const float4*)(qW + i * DH + lane * 4);
        acc[i] = hv.x * wq.x + hv.y * wq.y + hv.z * wq.z + hv.w * wq.w;
        float4 wk = *(const float4*)(kW + i * DH + lane * 4);
        acc[4 + i] = hv.x * wk.x + hv.y * wk.y + hv.z * wk.z + hv.w * wk.w;
    }
#pragma unroll
    for (int ofs = 16; ofs >= 1; ofs >>= 1)
#pragma unroll
        for (int i = 0; i < 8; i++) acc[i] += __shfl_xor_sync(FULL, acc[i], ofs);
    if (lane < 8) {
        float b = (lane < 4) ? qb[lane] : kb[lane - 4];
        float half = ftanh(acc[lane] + b) * (0.5f * PI_HALF);
        float s, c;
        __sincosf(half, &s, &c);
        if (lane < 4) {
            // fold the H gate: per-wire amps after RY(q) then H
            g_qtrig[n * 8 + lane]     = (c + s) * RSQRT2;   // bit = 0
            g_qtrig[n * 8 + 4 + lane] = (c - s) * RSQRT2;   // bit = 1
        } else {
            g_ktrig[n * 8 + lane - 4] = c;
            g_ktrig[n * 8 + lane]     = s;
        }
    }
    // ent circuit on lanes 0..15
    float h0 = __shfl_sync(FULL, hv.x, 0);
    float h1 = __shfl_sync(FULL, hv.y, 0);
    float h2 = __shfl_sync(FULL, hv.z, 0);
    float h3 = __shfl_sync(FULL, hv.w, 0);
    float myc = 1.f, mys = 0.f;
    if (lane < 4) {
        float myh = (lane == 0) ? h0 : (lane == 1) ? h1 : (lane == 2) ? h2 : h3;
        float a = ftanh(myh) * (0.5f * PI_HALF);
        __sincosf(a, &mys, &myc);
    }
    float c0 = __shfl_sync(FULL, myc, 0), s0 = __shfl_sync(FULL, mys, 0);
    float c1 = __shfl_sync(FULL, myc, 1), s1 = __shfl_sync(FULL, mys, 1);
    float c2 = __shfl_sync(FULL, myc, 2), s2 = __shfl_sync(FULL, mys, 2);
    float c3 = __shfl_sync(FULL, myc, 3), s3 = __shfl_sync(FULL, mys, 3);
    int L = lane & 15;
    float ar = (L & 8 ? s0 : c0) * (L & 4 ? s1 : c1) * (L & 2 ? s2 : c2) * (L & 1 ? s3 : c3);
    float ai = 0.f;
#pragma unroll
    for (int sub = 0; sub < 2; sub++) {
        cnot_shfl(ar, ai, L, 8, 4);
        cnot_shfl(ar, ai, L, 4, 2);
        cnot_shfl(ar, ai, L, 2, 1);
#pragma unroll
        for (int w = 0; w < 4; w++)
            rot_shfl(ar, ai, L, &g_rot[(rotbase + sub * 4 + w) * 8], 8 >> w);
        cnot_shfl(ar, ai, L, 8, 1);
    }
    float z0, z1, z2, z3;
    zexp_shfl(ar, ai, L, z0, z1, z2, z3);
    if (lane == 0)
        *(float4*)(g_xq + n * NQ) = make_float4(z0, z1, z2, z3);
}

__global__ void entqk_kernel(const float* __restrict__ h, int rotbase,
                             const float* __restrict__ qW, const float* __restrict__ qb,
                             const float* __restrict__ kW, const float* __restrict__ kb, int N)
{
    int warp = (blockIdx.x * blockDim.x + threadIdx.x) >> 5;
    int lane = threadIdx.x & 31;
    if (warp >= N) return;
    float4 hv = *(const float4*)(h + (size_t)warp * DH + lane * 4);
    node_body(hv, warp, lane, rotbase, qW, qb, kW, kb);
}

// ---------------- per-edge attention: CSR-slot order, observable-collapsed Rot ----------------
__global__ void edge_kernel(int E2, int layer)
{
    __shared__ float pre[8];   // wZ[4], wX[4]
    if (threadIdx.x < 8) pre[threadIdx.x] = g_attpre[layer * 8 + threadIdx.x];
    __syncthreads();

    int e = blockIdx.x * blockDim.x + threadIdx.x;
    float wgt = 0.f;
    if (e < E2) {
        int src = g_src[e];
        int dst = g_dst[e];
        const float4* qp = (const float4*)(g_qtrig + src * 8);
        const float4* kp = (const float4*)(g_ktrig + dst * 8);
        float4 qa = qp[0], qb = qp[1];   // H-folded per-wire amps
        float4 kc = kp[0], ks = kp[1];
        float aa[4] = {qa.x, qa.y, qa.z, qa.w};
        float bb[4] = {qb.x, qb.y, qb.z, qb.w};
        float v[16];
#pragma unroll
        for (int idx = 0; idx < 16; idx++)
            v[idx] = (idx & 8 ? bb[0] : aa[0]) * (idx & 4 ? bb[1] : aa[1]) *
                     (idx & 2 ? bb[2] : aa[2]) * (idx & 1 ? bb[3] : aa[3]);
        // CRY(k_i) on (i, (i+1)%4): real rotations on control=1 subspace
        float kcc[4] = {kc.x, kc.y, kc.z, kc.w};
        float kss[4] = {ks.x, ks.y, ks.z, ks.w};
#pragma unroll
        for (int i = 0; i < 4; i++) {
            float cs = kcc[i], sc = kss[i];
            int mc = 8 >> i, mt = 8 >> ((i + 1) & 3);
#pragma unroll
            for (int idx = 0; idx < 16; idx++) {
                if ((idx & mc) && !(idx & mt)) {
                    int j = idx | mt;
                    float a = v[idx], b = v[j];
                    v[idx] = cs * a - sc * b;
                    v[j]   = sc * a + cs * b;
                }
            }
        }
        // score = sum_i wZ_i * <Z_i> + wX_i * sum_{pairs_i} 2 v_j v_{j^m}
        float p[16];
#pragma unroll
        for (int idx = 0; idx < 16; idx++) p[idx] = v[idx] * v[idx];
        float score = 0.f;
#pragma unroll
        for (int i = 0; i < 4; i++) {
            int m = 8 >> i;
            float zs = 0.f, xs = 0.f;
#pragma unroll
            for (int idx = 0; idx < 16; idx++) {
                if (idx & m) zs -= p[idx];
                else { zs += p[idx]; xs += v[idx] * v[idx | m]; }
            }
            score += pre[i] * zs + pre[4 + i] * (2.f * xs);
        }
        wgt = __expf(score);
        g_att[e] = wgt;   // coalesced: already CSR order
    }
    __shared__ float sred[256];
    sred[threadIdx.x] = wgt;
    __syncthreads();
    for (int s = 128; s > 0; s >>= 1) {
        if (threadIdx.x < s) sred[threadIdx.x] += sred[threadIdx.x + s];
        __syncthreads();
    }
    if (threadIdx.x == 0) g_partial[blockIdx.x] = sred[0];

    __shared__ bool amLast;
    __threadfence();
    if (threadIdx.x == 0) {
        unsigned old = atomicAdd(&g_ctr, 1u);
        amLast = (old == gridDim.x - 1);
    }
    __syncthreads();
    if (amLast) {
        float a = 0.f;
        for (int i = threadIdx.x; i < gridDim.x; i += 256) a += g_partial[i];
        sred[threadIdx.x] = a;
        __syncthreads();
        for (int s = 128; s > 0; s >>= 1) {
            if (threadIdx.x < s) sred[threadIdx.x] += sred[threadIdx.x + s];
            __syncthreads();
        }
        if (threadIdx.x == 0) { g_expsum = sred[0]; g_ctr = 0u; }
    }
}

// ---------------- agg body ----------------
__device__ __forceinline__ float4 agg_row(int n, int lane)
{
    float inv = __frcp_rn(g_expsum);
    int beg = g_off[n], end = g_off[n + 1];
    float4 acc = make_float4(0.f, 0.f, 0.f, 0.f);
    int i = beg;
    for (; i + 3 < end; i += 4) {
        int   s0 = g_src[i],   s1 = g_src[i+1], s2 = g_src[i+2], s3 = g_src[i+3];
        float w0 = g_att[i],   w1 = g_att[i+1], w2 = g_att[i+2], w3 = g_att[i+3];
        float4 v0 = *(const float4*)(g_xc + (size_t)s0 * DH + lane * 4);
        float4 v1 = *(const float4*)(g_xc + (size_t)s1 * DH + lane * 4);
        float4 v2 = *(const float4*)(g_xc + (size_t)s2 * DH + lane * 4);
        float4 v3 = *(const float4*)(g_xc + (size_t)s3 * DH + lane * 4);
        acc.x += w0*v0.x + w1*v1.x + w2*v2.x + w3*v3.x;
        acc.y += w0*v0.y + w1*v1.y + w2*v2.y + w3*v3.y;
        acc.z += w0*v0.z + w1*v1.z + w2*v2.z + w3*v3.z;
        acc.w += w0*v0.w + w1*v1.w + w2*v2.w + w3*v3.w;
    }
    for (; i < end; i++) {
        float w = g_att[i];
        float4 v = *(const float4*)(g_xc + (size_t)g_src[i] * DH + lane * 4);
        acc.x += w*v.x; acc.y += w*v.y; acc.z += w*v.z; acc.w += w*v.w;
    }
    float4 o;
    o.x = fmaxf(acc.x * inv, 0.f);
    o.y = fmaxf(acc.y * inv, 0.f);
    o.z = fmaxf(acc.z * inv, 0.f);
    o.w = fmaxf(acc.w * inv, 0.f);
    return o;
}

// ---------------- agg + entqk fused ----------------
__global__ void aggentqk_kernel(float* __restrict__ hout, int rotbase,
                                const float* __restrict__ qW, const float* __restrict__ qb,
                                const float* __restrict__ kW, const float* __restrict__ kb, int N)
{
    int warp = (blockIdx.x * blockDim.x + threadIdx.x) >> 5;
    int lane = threadIdx.x & 31;
    if (warp >= N) return;
    float4 hv = agg_row(warp, lane);
    *(float4*)(hout + (size_t)warp * DH + lane * 4) = hv;
    node_body(hv, warp, lane, rotbase, qW, qb, kW, kb);
}

// ---------------- agg + final path circuit fused ----------------
__global__ void aggfinal_kernel(const float* __restrict__ piW, const float* __restrict__ pib,
                                float* __restrict__ out, int N)
{
    int warp = (blockIdx.x * blockDim.x + threadIdx.x) >> 5;
    int lane = threadIdx.x & 31;
    if (warp >= N) return;
    float4 hv = agg_row(warp, lane);

    float acc[4];
#pragma unroll
    for (int i = 0; i < 4; i++) {
        float4 w = *(const float4*)(piW + i * DH + lane * 4);
        acc[i] = hv.x * w.x + hv.y * w.y + hv.z * w.z + hv.w * w.w;
    }
#pragma unroll
    for (int ofs = 16; ofs >= 1; ofs >>= 1)
#pragma unroll
        for (int i = 0; i < 4; i++) acc[i] += __shfl_xor_sync(FULL, acc[i], ofs);

    float myb0 = 0.f, myb1 = 0.f;
    if (lane < 4) {
        float a = ftanh(acc[lane] + pib[lane]) * (0.5f * PI_HALF);
        float s, c;
        __sincosf(a, &s, &c);
        myb0 = (c - s) * RSQRT2;
        myb1 = (c + s) * RSQRT2;
    }
    float b00 = __shfl_sync(FULL, myb0, 0), b10 = __shfl_sync(FULL, myb1, 0);
    float b01 = __shfl_sync(FULL, myb0, 1), b11 = __shfl_sync(FULL, myb1, 1);
    float b02 = __shfl_sync(FULL, myb0, 2), b12 = __shfl_sync(FULL, myb1, 2);
    float b03 = __shfl_sync(FULL, myb0, 3), b13 = __shfl_sync(FULL, myb1, 3);
    int L = lane & 15;
    float ar = (L & 8 ? b10 : b00) * (L & 4 ? b11 : b01) * (L & 2 ? b12 : b02) * (L & 1 ? b13 : b03);
    float ai = 0.f;
#pragma unroll
    for (int l = 0; l < 3; l++) {
#pragma unroll
        for (int w = 0; w < 4; w++)
            rot_shfl(ar, ai, L, &g_rot[(24 + l * 4 + w) * 8], 8 >> w);
        cnot_shfl(ar, ai, L, 8, 4);
        cnot_shfl(ar, ai, L, 4, 2);
        cnot_shfl(ar, ai, L, 2, 1);
    }
    float z0, z1, z2, z3;
    zexp_shfl(ar, ai, L, z0, z1, z2, z3);
    z0 = __shfl_sync(FULL, z0, 0);
    z1 = __shfl_sync(FULL, z1, 0);
    z2 = __shfl_sync(FULL, z2, 0);
    z3 = __shfl_sync(FULL, z3, 0);
    float4 m = *(const float4*)(g_M + lane * 4);
    out[(size_t)warp * DOUT + lane] = z0 * m.x + z1 * m.y + z2 * m.z + z3 * m.w + g_C[lane];
}

// ---------------- host ----------------
extern "C" void kernel_launch(void* const* d_in, const int* in_sizes, int n_in,
                              void* d_out, int out_size)
{
    const float* x          = (const float*)d_in[0];
    const float* W_in       = (const float*)d_in[1];
    const float* b_in       = (const float*)d_in[2];
    const float* lin_W      = (const float*)d_in[3];
    const float* lin_b      = (const float*)d_in[4];
    const float* qproj_W    = (const float*)d_in[5];
    const float* qproj_b    = (const float*)d_in[6];
    const float* ent_params = (const float*)d_in[7];
    const float* attq_W     = (const float*)d_in[8];
    const float* attq_b     = (const float*)d_in[9];
    const float* attk_W     = (const float*)d_in[10];
    const float* attk_b     = (const float*)d_in[11];
    const float* att_qp     = (const float*)d_in[12];
    const float* path_params= (const float*)d_in[13];
    const float* path_in_W  = (const float*)d_in[14];
    const float* path_in_b  = (const float*)d_in[15];
    const float* path_out_W = (const float*)d_in[16];
    const float* path_out_b = (const float*)d_in[17];
    const float* out_W      = (const float*)d_in[18];
    const float* out_b      = (const float*)d_in[19];
    const int*   edge_index = (const int*)d_in[20];
    float* out = (float*)d_out;

    int N  = in_sizes[0] / DIN;
    int E  = in_sizes[20] / 2;
    int E2 = E + N;

    float *p_h, *p_hn, *p_xc;
    cudaGetSymbolAddress((void**)&p_h,  g_h);
    cudaGetSymbolAddress((void**)&p_hn, g_hn);
    cudaGetSymbolAddress((void**)&p_xc, g_xc);

    int eblocks  = (E2 + 255) / 256;
    int eblocks2 = (E2 + 511) / 512;
    int sblocks  = (N + 1023) / 1024;

    setup_kernel<<<(N + 256) / 256, 256>>>(ent_params, att_qp, path_params,
                                           path_out_W, path_out_b, out_W, out_b, N);
    count_kernel<<<eblocks2, 256>>>(edge_index, E, N);
    scan_kernel<<<sblocks, 1024>>>(N, sblocks);
    fill_kernel<<<eblocks2, 256>>>(edge_index, E, N);

    gemm64<<<(N + 63) / 64, 128>>>(x, W_in, b_in, p_h, N, DIN, 1, nullptr, nullptr);

    // layer 0
    entqk_kernel<<<(N + 7) / 8, 256>>>(p_h, 0, attq_W, attq_b, attk_W, attk_b, N);
    gemm64<<<(N + 63) / 64, 128>>>(p_h, lin_W, lin_b, p_xc, N, DH, 0, qproj_W, qproj_b);
    edge_kernel<<<eblocks, 256>>>(E2, 0);

    // layer 1
    aggentqk_kernel<<<(N + 7) / 8, 256>>>(p_hn, 8,
                                          attq_W + NQ * DH, attq_b + NQ,
                                          attk_W + NQ * DH, attk_b + NQ, N);
    gemm64<<<(N + 63) / 64, 128>>>(p_hn, lin_W + (size_t)DH * DH, lin_b + DH, p_xc, N, DH, 0,
                                   qproj_W + (size_t)DH * NQ, qproj_b + DH);
    edge_kernel<<<eblocks, 256>>>(E2, 1);

    // final
    aggfinal_kernel<<<(N + 7) / 8, 256>>>(path_in_W, path_in_b, out, N);
}